// round 3
// baseline (speedup 1.0000x reference)
#include <cuda_runtime.h>
#include <cstddef>

#define BATCH 64
#define NTOK  197
#define HW    1024
#define IMGW  32
#define KS    11
#define PADR  5
#define ALD   256   // padded alpha leading dim (>= 4 tiles of 64)

// ---------------- scratch (static device globals; no allocs allowed) --------
__device__ float g_q[(size_t)BATCH * NTOK * HW];
__device__ float g_k[(size_t)BATCH * NTOK * HW];
__device__ float g_v[(size_t)BATCH * NTOK * HW];
__device__ float g_alpha[(size_t)BATCH * NTOK * ALD];

// ---------------- 1) depthwise 11x11 SAME conv, 3 filters sharing taps ------
// grid (197, 64), block 256. Each thread computes a 1x4 pixel quad.
#define SIMG_LD 45   // odd stride -> conflict-free scalar LDS taps
__global__ void __launch_bounds__(256) dwconv_kernel(
    const float* __restrict__ x,
    const float* __restrict__ Wq,
    const float* __restrict__ Wk,
    const float* __restrict__ Wv)
{
    const int ch = blockIdx.x;
    const int b  = blockIdx.y;
    const int tid = threadIdx.x;

    __shared__ float simg[(IMGW + 2 * PADR) * SIMG_LD];  // 42 x 45
    __shared__ float wq[KS * KS], wk[KS * KS], wv[KS * KS];

    // zero the padded image
    for (int i = tid; i < (IMGW + 2 * PADR) * SIMG_LD; i += 256) simg[i] = 0.0f;
    if (tid < KS * KS) {
        wq[tid] = Wq[ch * KS * KS + tid];
        wk[tid] = Wk[ch * KS * KS + tid];
        wv[tid] = Wv[ch * KS * KS + tid];
    }
    __syncthreads();

    const float* xim = x + ((size_t)b * NTOK + ch) * HW;
    for (int i = tid; i < HW; i += 256) {
        int r = i >> 5, c = i & 31;
        simg[(r + PADR) * SIMG_LD + (c + PADR)] = xim[i];
    }
    __syncthreads();

    const int r  = tid >> 3;          // 0..31
    const int c0 = (tid & 7) << 2;    // 0,4,...,28

    float aq[4] = {0, 0, 0, 0}, ak[4] = {0, 0, 0, 0}, av[4] = {0, 0, 0, 0};

#pragma unroll
    for (int ky = 0; ky < KS; ky++) {
        const float* row = &simg[(r + ky) * SIMG_LD + c0];
        float xr[KS + 3];
#pragma unroll
        for (int t = 0; t < KS + 3; t++) xr[t] = row[t];
#pragma unroll
        for (int kx = 0; kx < KS; kx++) {
            const float wqv = wq[ky * KS + kx];
            const float wkv = wk[ky * KS + kx];
            const float wvv = wv[ky * KS + kx];
#pragma unroll
            for (int u = 0; u < 4; u++) {
                aq[u] = fmaf(xr[kx + u], wqv, aq[u]);
                ak[u] = fmaf(xr[kx + u], wkv, ak[u]);
                av[u] = fmaf(xr[kx + u], wvv, av[u]);
            }
        }
    }

    const size_t base = ((size_t)b * NTOK + ch) * HW + r * IMGW + c0;
    *(float4*)&g_q[base] = make_float4(aq[0], aq[1], aq[2], aq[3]);
    *(float4*)&g_k[base] = make_float4(ak[0], ak[1], ak[2], ak[3]);
    *(float4*)&g_v[base] = make_float4(av[0], av[1], av[2], av[3]);
}

// ---------------- 2) alpha = Q K^T / 32  (per-batch NT GEMM, K=1024) --------
// grid (4 j-tiles, 4 i-tiles, 64), block 256 (16x16), 4x4 microtile.
__global__ void __launch_bounds__(256) qk_gemm_kernel()
{
    const int b  = blockIdx.z;
    const int i0 = blockIdx.y * 64;
    const int j0 = blockIdx.x * 64;
    const int tid = threadIdx.x;
    const int tx = tid & 15, ty = tid >> 4;

    __shared__ __align__(16) float Qs[32][68];  // [k][i]
    __shared__ __align__(16) float Ks[32][68];  // [k][j]

    const float* Qb = g_q + (size_t)b * NTOK * HW;
    const float* Kb = g_k + (size_t)b * NTOK * HW;

    float acc[4][4] = {};

    const int lrow = tid >> 3;          // 0..31
    const int lcol = (tid & 7) << 2;    // k offset 0..28

    for (int k0 = 0; k0 < HW; k0 += 32) {
#pragma unroll
        for (int h = 0; h < 2; h++) {
            const int i = i0 + lrow + h * 32;
            float4 qv = make_float4(0, 0, 0, 0);
            if (i < NTOK) qv = *(const float4*)&Qb[(size_t)i * HW + k0 + lcol];
            Qs[lcol + 0][lrow + h * 32] = qv.x;
            Qs[lcol + 1][lrow + h * 32] = qv.y;
            Qs[lcol + 2][lrow + h * 32] = qv.z;
            Qs[lcol + 3][lrow + h * 32] = qv.w;

            const int j = j0 + lrow + h * 32;
            float4 kv = make_float4(0, 0, 0, 0);
            if (j < NTOK) kv = *(const float4*)&Kb[(size_t)j * HW + k0 + lcol];
            Ks[lcol + 0][lrow + h * 32] = kv.x;
            Ks[lcol + 1][lrow + h * 32] = kv.y;
            Ks[lcol + 2][lrow + h * 32] = kv.z;
            Ks[lcol + 3][lrow + h * 32] = kv.w;
        }
        __syncthreads();

#pragma unroll
        for (int kk = 0; kk < 32; kk++) {
            const float4 a4 = *(const float4*)&Qs[kk][ty * 4];
            const float4 b4 = *(const float4*)&Ks[kk][tx * 4];
            const float avv[4] = {a4.x, a4.y, a4.z, a4.w};
            const float bvv[4] = {b4.x, b4.y, b4.z, b4.w};
#pragma unroll
            for (int mi = 0; mi < 4; mi++)
#pragma unroll
                for (int nj = 0; nj < 4; nj++)
                    acc[mi][nj] = fmaf(avv[mi], bvv[nj], acc[mi][nj]);
        }
        __syncthreads();
    }

    const float scale = 1.0f / 32.0f;
#pragma unroll
    for (int mi = 0; mi < 4; mi++) {
        const int i = i0 + ty * 4 + mi;
        if (i < NTOK) {
            float4 o = make_float4(acc[mi][0] * scale, acc[mi][1] * scale,
                                   acc[mi][2] * scale, acc[mi][3] * scale);
            *(float4*)&g_alpha[((size_t)b * NTOK + i) * ALD + j0 + tx * 4] = o;
        }
    }
}

// ---------------- 3) row softmax over j (197 cols; pad cols stay 0) ---------
// block 256 = 8 warps; warp-shuffle reduction + tiny smem combine.
__global__ void __launch_bounds__(256) softmax_kernel()
{
    const int i = blockIdx.x;
    const int b = blockIdx.y;
    const int tid = threadIdx.x;
    const int lane = tid & 31, wid = tid >> 5;
    float* a = &g_alpha[((size_t)b * NTOK + i) * ALD];

    __shared__ float sred[8];

    float val = (tid < NTOK) ? a[tid] : -1e30f;

    // max reduce
    float m = val;
#pragma unroll
    for (int s = 16; s > 0; s >>= 1) m = fmaxf(m, __shfl_xor_sync(0xFFFFFFFF, m, s));
    if (lane == 0) sred[wid] = m;
    __syncthreads();
    if (wid == 0) {
        float t = sred[lane & 7];
#pragma unroll
        for (int s = 4; s > 0; s >>= 1) t = fmaxf(t, __shfl_xor_sync(0xFFFFFFFF, t, s));
        if (lane == 0) sred[0] = t;
    }
    __syncthreads();
    m = sred[0];
    __syncthreads();

    const float e = (tid < NTOK) ? expf(val - m) : 0.0f;

    // sum reduce
    float sum = e;
#pragma unroll
    for (int s = 16; s > 0; s >>= 1) sum += __shfl_xor_sync(0xFFFFFFFF, sum, s);
    if (lane == 0) sred[wid] = sum;
    __syncthreads();
    if (wid == 0) {
        float t = sred[lane & 7];
#pragma unroll
        for (int s = 4; s > 0; s >>= 1) t += __shfl_xor_sync(0xFFFFFFFF, t, s);
        if (lane == 0) sred[0] = t;
    }
    __syncthreads();
    const float inv = 1.0f / sred[0];

    if (tid < NTOK) a[tid] = e * inv;
}

// ---------------- 4) out = alpha V  (per-batch NN GEMM, K=256 padded) -------
// grid (16 s-tiles, 4 i-tiles, 64), block 256, 4x4 microtile.
__global__ void __launch_bounds__(256) av_gemm_kernel(float* __restrict__ out)
{
    const int b  = blockIdx.z;
    const int i0 = blockIdx.y * 64;
    const int s0 = blockIdx.x * 64;
    const int tid = threadIdx.x;
    const int tx = tid & 15, ty = tid >> 4;

    __shared__ __align__(16) float As[32][68];  // [j][i]
    __shared__ __align__(16) float Vs[32][64];  // [j][s]

    const float* Ab = g_alpha + (size_t)b * NTOK * ALD;
    const float* Vb = g_v + (size_t)b * NTOK * HW;

    float acc[4][4] = {};

    const int arow = tid >> 3;          // 0..31 (i offset)
    const int acol = (tid & 7) << 2;    // j offset 0..28
    const int vrow = tid >> 4;          // 0..15 (j offset)
    const int vcol = (tid & 15) << 2;   // s offset 0..60

    for (int k0 = 0; k0 < ALD; k0 += 32) {
#pragma unroll
        for (int h = 0; h < 2; h++) {
            const int i = i0 + arow + h * 32;
            float4 a4 = make_float4(0, 0, 0, 0);
            if (i < NTOK) a4 = *(const float4*)&Ab[(size_t)i * ALD + k0 + acol];
            As[acol + 0][arow + h * 32] = a4.x;
            As[acol + 1][arow + h * 32] = a4.y;
            As[acol + 2][arow + h * 32] = a4.z;
            As[acol + 3][arow + h * 32] = a4.w;

            const int j = k0 + vrow + h * 16;
            float4 v4 = make_float4(0, 0, 0, 0);
            if (j < NTOK) v4 = *(const float4*)&Vb[(size_t)j * HW + s0 + vcol];
            *(float4*)&Vs[vrow + h * 16][vcol] = v4;
        }
        __syncthreads();

#pragma unroll
        for (int kk = 0; kk < 32; kk++) {
            const float4 a4 = *(const float4*)&As[kk][ty * 4];
            const float4 b4 = *(const float4*)&Vs[kk][tx * 4];
            const float avv[4] = {a4.x, a4.y, a4.z, a4.w};
            const float bvv[4] = {b4.x, b4.y, b4.z, b4.w};
#pragma unroll
            for (int mi = 0; mi < 4; mi++)
#pragma unroll
                for (int nj = 0; nj < 4; nj++)
                    acc[mi][nj] = fmaf(avv[mi], bvv[nj], acc[mi][nj]);
        }
        __syncthreads();
    }

#pragma unroll
    for (int mi = 0; mi < 4; mi++) {
        const int i = i0 + ty * 4 + mi;
        if (i < NTOK) {
            float4 o = make_float4(acc[mi][0], acc[mi][1], acc[mi][2], acc[mi][3]);
            *(float4*)&out[((size_t)b * NTOK + i) * HW + s0 + tx * 4] = o;
        }
    }
}

// ---------------- launch ----------------------------------------------------
extern "C" void kernel_launch(void* const* d_in, const int* in_sizes, int n_in,
                              void* d_out, int out_size)
{
    const float* x  = (const float*)d_in[0];
    const float* Wq = (const float*)d_in[1];
    const float* Wk = (const float*)d_in[2];
    const float* Wv = (const float*)d_in[3];
    float* out = (float*)d_out;

    dim3 gConv(NTOK, BATCH);
    dwconv_kernel<<<gConv, 256>>>(x, Wq, Wk, Wv);

    dim3 gA(4, 4, BATCH);
    qk_gemm_kernel<<<gA, 256>>>();

    dim3 gS(NTOK, BATCH);
    softmax_kernel<<<gS, 256>>>();

    dim3 gB(16, 4, BATCH);
    av_gemm_kernel<<<gB, 256>>>(out);
}

// round 4
// speedup vs baseline: 1.1278x; 1.1278x over previous
#include <cuda_runtime.h>
#include <cstddef>

#define BATCH 64
#define NTOK  197
#define HW    1024
#define IMGW  32
#define KS    11
#define PADR  5
#define ALD   256   // padded alpha leading dim (2 tiles of 128)

// ---------------- scratch (static device globals; no allocs allowed) --------
__device__ float g_q[(size_t)BATCH * NTOK * HW];
__device__ float g_k[(size_t)BATCH * NTOK * HW];
__device__ float g_v[(size_t)BATCH * NTOK * HW];
__device__ float g_alpha[(size_t)BATCH * NTOK * ALD];

// ---------------- 1) depthwise 11x11 SAME conv, 3 filters sharing taps ------
#define SIMG_LD 45
__global__ void __launch_bounds__(256) dwconv_kernel(
    const float* __restrict__ x,
    const float* __restrict__ Wq,
    const float* __restrict__ Wk,
    const float* __restrict__ Wv)
{
    const int ch = blockIdx.x;
    const int b  = blockIdx.y;
    const int tid = threadIdx.x;

    __shared__ float simg[(IMGW + 2 * PADR) * SIMG_LD];  // 42 x 45
    __shared__ float wq[KS * KS], wk[KS * KS], wv[KS * KS];

    for (int i = tid; i < (IMGW + 2 * PADR) * SIMG_LD; i += 256) simg[i] = 0.0f;
    if (tid < KS * KS) {
        wq[tid] = Wq[ch * KS * KS + tid];
        wk[tid] = Wk[ch * KS * KS + tid];
        wv[tid] = Wv[ch * KS * KS + tid];
    }
    __syncthreads();

    const float* xim = x + ((size_t)b * NTOK + ch) * HW;
    for (int i = tid; i < HW; i += 256) {
        int r = i >> 5, c = i & 31;
        simg[(r + PADR) * SIMG_LD + (c + PADR)] = xim[i];
    }
    __syncthreads();

    const int r  = tid >> 3;          // 0..31
    const int c0 = (tid & 7) << 2;    // 0,4,...,28

    float aq[4] = {0, 0, 0, 0}, ak[4] = {0, 0, 0, 0}, av[4] = {0, 0, 0, 0};

#pragma unroll
    for (int ky = 0; ky < KS; ky++) {
        const float* row = &simg[(r + ky) * SIMG_LD + c0];
        float xr[KS + 3];
#pragma unroll
        for (int t = 0; t < KS + 3; t++) xr[t] = row[t];
#pragma unroll
        for (int kx = 0; kx < KS; kx++) {
            const float wqv = wq[ky * KS + kx];
            const float wkv = wk[ky * KS + kx];
            const float wvv = wv[ky * KS + kx];
#pragma unroll
            for (int u = 0; u < 4; u++) {
                aq[u] = fmaf(xr[kx + u], wqv, aq[u]);
                ak[u] = fmaf(xr[kx + u], wkv, ak[u]);
                av[u] = fmaf(xr[kx + u], wvv, av[u]);
            }
        }
    }

    const size_t base = ((size_t)b * NTOK + ch) * HW + r * IMGW + c0;
    *(float4*)&g_q[base] = make_float4(aq[0], aq[1], aq[2], aq[3]);
    *(float4*)&g_k[base] = make_float4(ak[0], ak[1], ak[2], ak[3]);
    *(float4*)&g_v[base] = make_float4(av[0], av[1], av[2], av[3]);
}

// ---------------- 2) alpha = Q K^T / 32  (per-batch NT GEMM, K=1024) --------
// grid (2 j-tiles, 2 i-tiles, 64), block 256. 128x128 tile, BK=16, 8x8 micro.
__global__ void __launch_bounds__(256) qk_gemm_kernel()
{
    const int b  = blockIdx.z;
    const int i0 = blockIdx.y * 128;
    const int j0 = blockIdx.x * 128;
    const int tid = threadIdx.x;
    const int tx = tid & 15, ty = tid >> 4;

    __shared__ __align__(16) float As[16][132];  // [k][i]
    __shared__ __align__(16) float Bs[16][132];  // [k][j]

    const float* Qb = g_q + (size_t)b * NTOK * HW;
    const float* Kb = g_k + (size_t)b * NTOK * HW;

    float acc[8][8] = {};

    const int lrow = tid >> 2;          // 0..63
    const int lcol = (tid & 3) << 2;    // k offset 0,4,8,12

    for (int k0 = 0; k0 < HW; k0 += 16) {
#pragma unroll
        for (int h = 0; h < 2; h++) {
            const int row = lrow + h * 64;
            const int i = i0 + row;
            float4 qv = make_float4(0, 0, 0, 0);
            if (i < NTOK) qv = *(const float4*)&Qb[(size_t)i * HW + k0 + lcol];
            As[lcol + 0][row] = qv.x;
            As[lcol + 1][row] = qv.y;
            As[lcol + 2][row] = qv.z;
            As[lcol + 3][row] = qv.w;

            const int j = j0 + row;
            float4 kv = make_float4(0, 0, 0, 0);
            if (j < NTOK) kv = *(const float4*)&Kb[(size_t)j * HW + k0 + lcol];
            Bs[lcol + 0][row] = kv.x;
            Bs[lcol + 1][row] = kv.y;
            Bs[lcol + 2][row] = kv.z;
            Bs[lcol + 3][row] = kv.w;
        }
        __syncthreads();

#pragma unroll
        for (int kk = 0; kk < 16; kk++) {
            const float4 a0 = *(const float4*)&As[kk][ty * 4];
            const float4 a1 = *(const float4*)&As[kk][64 + ty * 4];
            const float4 b0 = *(const float4*)&Bs[kk][tx * 4];
            const float4 b1 = *(const float4*)&Bs[kk][64 + tx * 4];
            const float am[8] = {a0.x, a0.y, a0.z, a0.w, a1.x, a1.y, a1.z, a1.w};
            const float bn[8] = {b0.x, b0.y, b0.z, b0.w, b1.x, b1.y, b1.z, b1.w};
#pragma unroll
            for (int mi = 0; mi < 8; mi++)
#pragma unroll
                for (int nj = 0; nj < 8; nj++)
                    acc[mi][nj] = fmaf(am[mi], bn[nj], acc[mi][nj]);
        }
        __syncthreads();
    }

    const float scale = 1.0f / 32.0f;
#pragma unroll
    for (int mi = 0; mi < 8; mi++) {
        const int i = i0 + (mi < 4 ? ty * 4 + mi : 64 + ty * 4 + mi - 4);
        if (i < NTOK) {
            float* arow = &g_alpha[((size_t)b * NTOK + i) * ALD + j0];
            float4 o0 = make_float4(acc[mi][0] * scale, acc[mi][1] * scale,
                                    acc[mi][2] * scale, acc[mi][3] * scale);
            float4 o1 = make_float4(acc[mi][4] * scale, acc[mi][5] * scale,
                                    acc[mi][6] * scale, acc[mi][7] * scale);
            *(float4*)&arow[tx * 4]      = o0;
            *(float4*)&arow[64 + tx * 4] = o1;
        }
    }
}

// ---------------- 3) row softmax over j (197 cols; pad cols stay 0) ---------
__global__ void __launch_bounds__(256) softmax_kernel()
{
    const int i = blockIdx.x;
    const int b = blockIdx.y;
    const int tid = threadIdx.x;
    const int lane = tid & 31, wid = tid >> 5;
    float* a = &g_alpha[((size_t)b * NTOK + i) * ALD];

    __shared__ float sred[8];

    float val = (tid < NTOK) ? a[tid] : -1e30f;

    float m = val;
#pragma unroll
    for (int s = 16; s > 0; s >>= 1) m = fmaxf(m, __shfl_xor_sync(0xFFFFFFFF, m, s));
    if (lane == 0) sred[wid] = m;
    __syncthreads();
    if (wid == 0) {
        float t = sred[lane & 7];
#pragma unroll
        for (int s = 4; s > 0; s >>= 1) t = fmaxf(t, __shfl_xor_sync(0xFFFFFFFF, t, s));
        if (lane == 0) sred[0] = t;
    }
    __syncthreads();
    m = sred[0];
    __syncthreads();

    const float e = (tid < NTOK) ? expf(val - m) : 0.0f;

    float sum = e;
#pragma unroll
    for (int s = 16; s > 0; s >>= 1) sum += __shfl_xor_sync(0xFFFFFFFF, sum, s);
    if (lane == 0) sred[wid] = sum;
    __syncthreads();
    if (wid == 0) {
        float t = sred[lane & 7];
#pragma unroll
        for (int s = 4; s > 0; s >>= 1) t += __shfl_xor_sync(0xFFFFFFFF, t, s);
        if (lane == 0) sred[0] = t;
    }
    __syncthreads();
    const float inv = 1.0f / sred[0];

    if (tid < NTOK) a[tid] = e * inv;
}

// ---------------- 4) out = alpha V  (per-batch NN GEMM, K=256 padded) -------
// grid (8 s-tiles, 2 i-tiles, 64), block 256. 128x128 tile, BK=16, 8x8 micro.
__global__ void __launch_bounds__(256) av_gemm_kernel(float* __restrict__ out)
{
    const int b  = blockIdx.z;
    const int i0 = blockIdx.y * 128;
    const int s0 = blockIdx.x * 128;
    const int tid = threadIdx.x;
    const int tx = tid & 15, ty = tid >> 4;

    __shared__ __align__(16) float As[16][132];  // [j][i]
    __shared__ __align__(16) float Vs[16][128];  // [j][s]

    const float* Ab = g_alpha + (size_t)b * NTOK * ALD;
    const float* Vb = g_v + (size_t)b * NTOK * HW;

    float acc[8][8] = {};

    const int arow = tid >> 2;          // 0..63 (i offset)
    const int acol = (tid & 3) << 2;    // j offset 0,4,8,12
    const int vrow = tid >> 5;          // 0..7 (j offset)
    const int vcol = (tid & 31) << 2;   // s offset 0..124

    for (int k0 = 0; k0 < ALD; k0 += 16) {
#pragma unroll
        for (int h = 0; h < 2; h++) {
            const int row = arow + h * 64;
            const int i = i0 + row;
            float4 a4 = make_float4(0, 0, 0, 0);
            if (i < NTOK) a4 = *(const float4*)&Ab[(size_t)i * ALD + k0 + acol];
            As[acol + 0][row] = a4.x;
            As[acol + 1][row] = a4.y;
            As[acol + 2][row] = a4.z;
            As[acol + 3][row] = a4.w;

            const int jr = vrow + h * 8;
            const int j = k0 + jr;
            float4 v4 = make_float4(0, 0, 0, 0);
            if (j < NTOK) v4 = *(const float4*)&Vb[(size_t)j * HW + s0 + vcol];
            *(float4*)&Vs[jr][vcol] = v4;
        }
        __syncthreads();

#pragma unroll
        for (int kk = 0; kk < 16; kk++) {
            const float4 a0 = *(const float4*)&As[kk][ty * 4];
            const float4 a1 = *(const float4*)&As[kk][64 + ty * 4];
            const float4 b0 = *(const float4*)&Vs[kk][tx * 4];
            const float4 b1 = *(const float4*)&Vs[kk][64 + tx * 4];
            const float am[8] = {a0.x, a0.y, a0.z, a0.w, a1.x, a1.y, a1.z, a1.w};
            const float bn[8] = {b0.x, b0.y, b0.z, b0.w, b1.x, b1.y, b1.z, b1.w};
#pragma unroll
            for (int mi = 0; mi < 8; mi++)
#pragma unroll
                for (int nj = 0; nj < 8; nj++)
                    acc[mi][nj] = fmaf(am[mi], bn[nj], acc[mi][nj]);
        }
        __syncthreads();
    }

#pragma unroll
    for (int mi = 0; mi < 8; mi++) {
        const int i = i0 + (mi < 4 ? ty * 4 + mi : 64 + ty * 4 + mi - 4);
        if (i < NTOK) {
            float* orow = &out[((size_t)b * NTOK + i) * HW + s0];
            float4 o0 = make_float4(acc[mi][0], acc[mi][1], acc[mi][2], acc[mi][3]);
            float4 o1 = make_float4(acc[mi][4], acc[mi][5], acc[mi][6], acc[mi][7]);
            *(float4*)&orow[tx * 4]      = o0;
            *(float4*)&orow[64 + tx * 4] = o1;
        }
    }
}

// ---------------- launch ----------------------------------------------------
extern "C" void kernel_launch(void* const* d_in, const int* in_sizes, int n_in,
                              void* d_out, int out_size)
{
    const float* x  = (const float*)d_in[0];
    const float* Wq = (const float*)d_in[1];
    const float* Wk = (const float*)d_in[2];
    const float* Wv = (const float*)d_in[3];
    float* out = (float*)d_out;

    dim3 gConv(NTOK, BATCH);
    dwconv_kernel<<<gConv, 256>>>(x, Wq, Wk, Wv);

    dim3 gA(2, 2, BATCH);
    qk_gemm_kernel<<<gA, 256>>>();

    dim3 gS(NTOK, BATCH);
    softmax_kernel<<<gS, 256>>>();

    dim3 gB(8, 2, BATCH);
    av_gemm_kernel<<<gB, 256>>>(out);
}

// round 6
// speedup vs baseline: 1.2381x; 1.0977x over previous
#include <cuda_runtime.h>
#include <cuda_bf16.h>
#include <cstdint>
#include <cstddef>

#define BATCH 64
#define NTOK  197
#define HW    1024
#define IMGW  32
#define KS    11
#define PADR  5
#define ALD   256   // padded token dim (j) for alpha / V^T

// ---------------- scratch (static device globals; no allocs allowed) --------
__device__ __nv_bfloat16 g_qh[(size_t)BATCH * NTOK * HW];
__device__ __nv_bfloat16 g_ql[(size_t)BATCH * NTOK * HW];
__device__ __nv_bfloat16 g_kh[(size_t)BATCH * NTOK * HW];
__device__ __nv_bfloat16 g_kl[(size_t)BATCH * NTOK * HW];
__device__ float         g_v [(size_t)BATCH * NTOK * HW];
__device__ __nv_bfloat16 g_vth[(size_t)BATCH * HW * ALD];   // V^T hi  [b][s][j]
__device__ __nv_bfloat16 g_vtl[(size_t)BATCH * HW * ALD];   // V^T lo
__device__ float         g_alpha[(size_t)BATCH * NTOK * ALD];
__device__ __nv_bfloat16 g_ah[(size_t)BATCH * NTOK * ALD];  // softmax(alpha) hi
__device__ __nv_bfloat16 g_al[(size_t)BATCH * NTOK * ALD];  // softmax(alpha) lo

// ---------------- helpers ----------------------------------------------------
__device__ __forceinline__ uint32_t smem_u32(const void* p) {
    uint32_t a;
    asm("{ .reg .u64 t; cvta.to.shared.u64 t, %1; cvt.u32.u64 %0, t; }"
        : "=r"(a) : "l"(p));
    return a;
}
#define SWZ(o) ((o) ^ (((o) >> 3) & 0x70))

__device__ __forceinline__ void ldsm4(uint32_t* r, uint32_t addr) {
    asm volatile("ldmatrix.sync.aligned.m8n8.x4.shared.b16 {%0,%1,%2,%3}, [%4];"
                 : "=r"(r[0]), "=r"(r[1]), "=r"(r[2]), "=r"(r[3]) : "r"(addr));
}
__device__ __forceinline__ void mma16816(float* d, const uint32_t* a,
                                         uint32_t b0, uint32_t b1) {
    asm volatile(
        "mma.sync.aligned.m16n8k16.row.col.f32.bf16.bf16.f32 "
        "{%0,%1,%2,%3}, {%4,%5,%6,%7}, {%8,%9}, {%0,%1,%2,%3};"
        : "+f"(d[0]), "+f"(d[1]), "+f"(d[2]), "+f"(d[3])
        : "r"(a[0]), "r"(a[1]), "r"(a[2]), "r"(a[3]), "r"(b0), "r"(b1));
}

// ---------------- shared GEMM body: C[128x128] += A[128xK] * B[128xK]^T ------
// A rows = M (row-major, k contiguous), B rows = N (row-major, k contiguous).
// bf16 hi/lo split: acc += Ah*Bh + Ah*Bl + Al*Bh.  BK=64 (128B rows, SW128).
// block = 256 threads = 8 warps as 4(M) x 2(N); warp tile 32x64.
__device__ __forceinline__ void run_gemm(
    const __nv_bfloat16* __restrict__ Ah, const __nv_bfloat16* __restrict__ Al,
    int lda, int aRows,
    const __nv_bfloat16* __restrict__ Bh, const __nv_bfloat16* __restrict__ Bl,
    int ldb, int bRows,
    int kTotal, char* smem, float acc[2][8][4])
{
    const int tid = threadIdx.x, lane = tid & 31, wid = tid >> 5;
    const int wm = wid >> 1, wn = wid & 1;
    char* sAh = smem;
    char* sAl = smem + 16384;
    char* sBh = smem + 32768;
    char* sBl = smem + 49152;
    const uint32_t sb = smem_u32(smem);

    for (int k0 = 0; k0 < kTotal; k0 += 64) {
        for (int idx = tid; idx < 1024; idx += 256) {
            const int row = idx >> 3, seg = idx & 7;
            const uint32_t sw = SWZ((uint32_t)(row * 128 + seg * 16));
            uint4 vh = make_uint4(0, 0, 0, 0), vl = make_uint4(0, 0, 0, 0);
            if (row < aRows) {
                vh = *(const uint4*)((const char*)(Ah + (size_t)row * lda + k0) + seg * 16);
                vl = *(const uint4*)((const char*)(Al + (size_t)row * lda + k0) + seg * 16);
            }
            *(uint4*)(sAh + sw) = vh;
            *(uint4*)(sAl + sw) = vl;

            uint4 wh = make_uint4(0, 0, 0, 0), wl = make_uint4(0, 0, 0, 0);
            if (row < bRows) {
                wh = *(const uint4*)((const char*)(Bh + (size_t)row * ldb + k0) + seg * 16);
                wl = *(const uint4*)((const char*)(Bl + (size_t)row * ldb + k0) + seg * 16);
            }
            *(uint4*)(sBh + sw) = wh;
            *(uint4*)(sBl + sw) = wl;
        }
        __syncthreads();

#pragma unroll
        for (int k16 = 0; k16 < 4; k16++) {
            const int kseg = k16 * 2 + (lane >> 4);
            uint32_t ah[2][4], al[2][4];
#pragma unroll
            for (int mt = 0; mt < 2; mt++) {
                const int row = wm * 32 + mt * 16 + (lane & 15);
                const uint32_t off = SWZ((uint32_t)(row * 128 + kseg * 16));
                ldsm4(ah[mt], sb + off);
                ldsm4(al[mt], sb + 16384 + off);
            }
            uint32_t bh[4][4], bl[4][4];
#pragma unroll
            for (int nt = 0; nt < 4; nt++) {
                const int row = wn * 64 + nt * 16 + (lane & 15);
                const uint32_t off = SWZ((uint32_t)(row * 128 + kseg * 16));
                ldsm4(bh[nt], sb + 32768 + off);
                ldsm4(bl[nt], sb + 49152 + off);
            }
#pragma unroll
            for (int mt = 0; mt < 2; mt++)
#pragma unroll
                for (int nt = 0; nt < 4; nt++)
#pragma unroll
                    for (int h = 0; h < 2; h++) {
                        float* d = acc[mt][nt * 2 + h];
                        const uint32_t h0 = bh[nt][h], h1 = bh[nt][h + 2];
                        mma16816(d, ah[mt], h0, h1);
                        mma16816(d, ah[mt], bl[nt][h], bl[nt][h + 2]);
                        mma16816(d, al[mt], h0, h1);
                    }
        }
        __syncthreads();
    }
}

// ---------------- 1) depthwise 11x11 SAME conv, 3 filters sharing taps ------
#define SIMG_LD 45
__device__ __forceinline__ void st_split4(__nv_bfloat16* ph, __nv_bfloat16* pl,
                                          const float* v) {
#pragma unroll
    for (int u = 0; u < 4; u += 2) {
        __nv_bfloat162 h, l;
        h.x = __float2bfloat16(v[u]);
        h.y = __float2bfloat16(v[u + 1]);
        l.x = __float2bfloat16(v[u]     - __bfloat162float(h.x));
        l.y = __float2bfloat16(v[u + 1] - __bfloat162float(h.y));
        *(__nv_bfloat162*)(ph + u) = h;
        *(__nv_bfloat162*)(pl + u) = l;
    }
}

__global__ void __launch_bounds__(256) dwconv_kernel(
    const float* __restrict__ x,
    const float* __restrict__ Wq,
    const float* __restrict__ Wk,
    const float* __restrict__ Wv)
{
    const int ch = blockIdx.x;
    const int b  = blockIdx.y;
    const int tid = threadIdx.x;

    __shared__ float simg[(IMGW + 2 * PADR) * SIMG_LD];  // 42 x 45
    __shared__ float wq[KS * KS], wk[KS * KS], wv[KS * KS];

    for (int i = tid; i < (IMGW + 2 * PADR) * SIMG_LD; i += 256) simg[i] = 0.0f;
    if (tid < KS * KS) {
        wq[tid] = Wq[ch * KS * KS + tid];
        wk[tid] = Wk[ch * KS * KS + tid];
        wv[tid] = Wv[ch * KS * KS + tid];
    }
    __syncthreads();

    const float* xim = x + ((size_t)b * NTOK + ch) * HW;
    for (int i = tid; i < HW; i += 256) {
        int r = i >> 5, c = i & 31;
        simg[(r + PADR) * SIMG_LD + (c + PADR)] = xim[i];
    }
    __syncthreads();

    const int r  = tid >> 3;
    const int c0 = (tid & 7) << 2;

    float aq[4] = {0, 0, 0, 0}, ak[4] = {0, 0, 0, 0}, av[4] = {0, 0, 0, 0};

#pragma unroll
    for (int ky = 0; ky < KS; ky++) {
        const float* row = &simg[(r + ky) * SIMG_LD + c0];
        float xr[KS + 3];
#pragma unroll
        for (int t = 0; t < KS + 3; t++) xr[t] = row[t];
#pragma unroll
        for (int kx = 0; kx < KS; kx++) {
            const float wqv = wq[ky * KS + kx];
            const float wkv = wk[ky * KS + kx];
            const float wvv = wv[ky * KS + kx];
#pragma unroll
            for (int u = 0; u < 4; u++) {
                aq[u] = fmaf(xr[kx + u], wqv, aq[u]);
                ak[u] = fmaf(xr[kx + u], wkv, ak[u]);
                av[u] = fmaf(xr[kx + u], wvv, av[u]);
            }
        }
    }

    const size_t base = ((size_t)b * NTOK + ch) * HW + r * IMGW + c0;
    st_split4(&g_qh[base], &g_ql[base], aq);
    st_split4(&g_kh[base], &g_kl[base], ak);
    *(float4*)&g_v[base] = make_float4(av[0], av[1], av[2], av[3]);
}

// ---------------- 2) V transpose: [b,j,s] fp32 -> [b,s,j] bf16 hi/lo --------
__global__ void __launch_bounds__(256) vtrans_kernel()
{
    const int s0 = blockIdx.x * 32;
    const int j0 = blockIdx.y * 32;
    const int b  = blockIdx.z;
    const int tx = threadIdx.x;   // 0..31
    const int ty = threadIdx.y;   // 0..7

    __shared__ float t[32][33];

#pragma unroll
    for (int k = 0; k < 4; k++) {
        int j = j0 + ty + k * 8;
        float v = 0.0f;
        if (j < NTOK) v = g_v[((size_t)b * NTOK + j) * HW + s0 + tx];
        t[ty + k * 8][tx] = v;
    }
    __syncthreads();

#pragma unroll
    for (int k = 0; k < 4; k++) {
        int sr = s0 + ty + k * 8;
        float v = t[tx][ty + k * 8];
        __nv_bfloat16 hi = __float2bfloat16(v);
        float lo = v - __bfloat162float(hi);
        size_t o = ((size_t)b * HW + sr) * ALD + j0 + tx;
        g_vth[o] = hi;
        g_vtl[o] = __float2bfloat16(lo);
    }
}

// ---------------- 3) alpha = Q K^T / 32 via mma.sync ------------------------
__global__ void __launch_bounds__(256) qk_mma_kernel()
{
    extern __shared__ __align__(128) char smem[];
    const int b  = blockIdx.z;
    const int i0 = blockIdx.y * 128;
    const int j0 = blockIdx.x * 128;
    const int tid = threadIdx.x, lane = tid & 31, wid = tid >> 5;
    const int wm = wid >> 1, wn = wid & 1;

    float acc[2][8][4] = {};
    const size_t ob = (size_t)b * NTOK * HW;
    run_gemm(g_qh + ob + (size_t)i0 * HW, g_ql + ob + (size_t)i0 * HW, HW, NTOK - i0,
             g_kh + ob + (size_t)j0 * HW, g_kl + ob + (size_t)j0 * HW, HW, NTOK - j0,
             HW, smem, acc);

    const float scale = 1.0f / 32.0f;
#pragma unroll
    for (int mt = 0; mt < 2; mt++)
#pragma unroll
        for (int nt = 0; nt < 4; nt++)
#pragma unroll
            for (int h = 0; h < 2; h++) {
                const float* d = acc[mt][nt * 2 + h];
                const int col = j0 + wn * 64 + nt * 16 + h * 8 + (lane & 3) * 2;
                const int r0  = i0 + wm * 32 + mt * 16 + (lane >> 2);
                if (r0 < NTOK) {
                    float* p = &g_alpha[((size_t)b * NTOK + r0) * ALD + col];
                    p[0] = d[0] * scale; p[1] = d[1] * scale;
                }
                if (r0 + 8 < NTOK) {
                    float* p = &g_alpha[((size_t)b * NTOK + r0 + 8) * ALD + col];
                    p[0] = d[2] * scale; p[1] = d[3] * scale;
                }
            }
}

// ---------------- 4) row softmax -> bf16 hi/lo (pads -> 0) ------------------
__global__ void __launch_bounds__(256) softmax_kernel()
{
    const int i = blockIdx.x;
    const int b = blockIdx.y;
    const int tid = threadIdx.x;
    const int lane = tid & 31, wid = tid >> 5;
    const float* a = &g_alpha[((size_t)b * NTOK + i) * ALD];

    __shared__ float sred[8];

    float val = (tid < NTOK) ? a[tid] : -1e30f;

    float m = val;
#pragma unroll
    for (int s = 16; s > 0; s >>= 1) m = fmaxf(m, __shfl_xor_sync(0xFFFFFFFF, m, s));
    if (lane == 0) sred[wid] = m;
    __syncthreads();
    if (wid == 0) {
        float t = sred[lane & 7];
#pragma unroll
        for (int s = 4; s > 0; s >>= 1) t = fmaxf(t, __shfl_xor_sync(0xFFFFFFFF, t, s));
        if (lane == 0) sred[0] = t;
    }
    __syncthreads();
    m = sred[0];
    __syncthreads();

    const float e = (tid < NTOK) ? expf(val - m) : 0.0f;

    float sum = e;
#pragma unroll
    for (int s = 16; s > 0; s >>= 1) sum += __shfl_xor_sync(0xFFFFFFFF, sum, s);
    if (lane == 0) sred[wid] = sum;
    __syncthreads();
    if (wid == 0) {
        float t = sred[lane & 7];
#pragma unroll
        for (int s = 4; s > 0; s >>= 1) t += __shfl_xor_sync(0xFFFFFFFF, t, s);
        if (lane == 0) sred[0] = t;
    }
    __syncthreads();

    const float r = (tid < NTOK) ? e * (1.0f / sred[0]) : 0.0f;
    __nv_bfloat16 hi = __float2bfloat16(r);
    const size_t o = ((size_t)b * NTOK + i) * ALD + tid;
    g_ah[o] = hi;
    g_al[o] = __float2bfloat16(r - __bfloat162float(hi));
}

// ---------------- 5) out = alpha V via mma.sync -----------------------------
__global__ void __launch_bounds__(256) av_mma_kernel(float* __restrict__ out)
{
    extern __shared__ __align__(128) char smem[];
    const int b  = blockIdx.z;
    const int i0 = blockIdx.y * 128;
    const int s0 = blockIdx.x * 128;
    const int tid = threadIdx.x, lane = tid & 31, wid = tid >> 5;
    const int wm = wid >> 1, wn = wid & 1;

    float acc[2][8][4] = {};
    const size_t ab = (size_t)b * NTOK * ALD;
    const size_t vb = (size_t)b * HW * ALD;
    run_gemm(g_ah + ab + (size_t)i0 * ALD, g_al + ab + (size_t)i0 * ALD, ALD, NTOK - i0,
             g_vth + vb + (size_t)s0 * ALD, g_vtl + vb + (size_t)s0 * ALD, ALD, 128,
             ALD, smem, acc);

#pragma unroll
    for (int mt = 0; mt < 2; mt++)
#pragma unroll
        for (int nt = 0; nt < 4; nt++)
#pragma unroll
            for (int h = 0; h < 2; h++) {
                const float* d = acc[mt][nt * 2 + h];
                const int col = s0 + wn * 64 + nt * 16 + h * 8 + (lane & 3) * 2;
                const int r0  = i0 + wm * 32 + mt * 16 + (lane >> 2);
                if (r0 < NTOK) {
                    float* p = &out[((size_t)b * NTOK + r0) * HW + col];
                    p[0] = d[0]; p[1] = d[1];
                }
                if (r0 + 8 < NTOK) {
                    float* p = &out[((size_t)b * NTOK + r0 + 8) * HW + col];
                    p[0] = d[2]; p[1] = d[3];
                }
            }
}

// ---------------- launch ----------------------------------------------------
#define GEMM_SMEM 65536

extern "C" void kernel_launch(void* const* d_in, const int* in_sizes, int n_in,
                              void* d_out, int out_size)
{
    const float* x  = (const float*)d_in[0];
    const float* Wq = (const float*)d_in[1];
    const float* Wk = (const float*)d_in[2];
    const float* Wv = (const float*)d_in[3];
    float* out = (float*)d_out;

    static int configured = 0;
    if (!configured) {
        cudaFuncSetAttribute(qk_mma_kernel,
                             cudaFuncAttributeMaxDynamicSharedMemorySize, GEMM_SMEM);
        cudaFuncSetAttribute(av_mma_kernel,
                             cudaFuncAttributeMaxDynamicSharedMemorySize, GEMM_SMEM);
        configured = 1;
    }

    dim3 gConv(NTOK, BATCH);
    dwconv_kernel<<<gConv, 256>>>(x, Wq, Wk, Wv);

    dim3 gT(32, 8, BATCH);
    vtrans_kernel<<<gT, dim3(32, 8)>>>();

    dim3 gQK(2, 2, BATCH);
    qk_mma_kernel<<<gQK, 256, GEMM_SMEM>>>();

    dim3 gS(NTOK, BATCH);
    softmax_kernel<<<gS, 256>>>();

    dim3 gAV(8, 2, BATCH);
    av_mma_kernel<<<gAV, 256, GEMM_SMEM>>>(out);
}

// round 8
// speedup vs baseline: 1.6697x; 1.3486x over previous
#include <cuda_runtime.h>
#include <cuda_bf16.h>
#include <cstdint>
#include <cstddef>

#define BATCH 64
#define NTOK  197
#define HW    1024
#define IMGW  32
#define KS    11
#define PADR  5
#define ALD   256   // padded token dim (j) for alpha / V^T

// ---------------- scratch (static device globals; no allocs allowed) --------
__device__ __nv_bfloat16 g_qh[(size_t)BATCH * NTOK * HW];
__device__ __nv_bfloat16 g_ql[(size_t)BATCH * NTOK * HW];
__device__ __nv_bfloat16 g_kh[(size_t)BATCH * NTOK * HW];
__device__ __nv_bfloat16 g_kl[(size_t)BATCH * NTOK * HW];
__device__ float         g_v [(size_t)BATCH * NTOK * HW];
__device__ __nv_bfloat16 g_vth[(size_t)BATCH * HW * ALD];   // V^T hi  [b][s][j]
__device__ __nv_bfloat16 g_vtl[(size_t)BATCH * HW * ALD];   // V^T lo
__device__ float         g_alpha[(size_t)BATCH * NTOK * ALD];
__device__ __nv_bfloat16 g_ah[(size_t)BATCH * NTOK * ALD];  // softmax(alpha) hi
__device__ __nv_bfloat16 g_al[(size_t)BATCH * NTOK * ALD];  // softmax(alpha) lo

// ---------------- helpers ----------------------------------------------------
__device__ __forceinline__ uint32_t smem_u32(const void* p) {
    uint32_t a;
    asm("{ .reg .u64 t; cvta.to.shared.u64 t, %1; cvt.u32.u64 %0, t; }"
        : "=r"(a) : "l"(p));
    return a;
}
// swizzle for 64-byte rows (8-row/512B atom): granules all distinct per 8 rows
#define SWZ64(o) ((o) ^ (((o) >> 3) & 0x30))

__device__ __forceinline__ void ldsm4(uint32_t* r, uint32_t addr) {
    asm volatile("ldmatrix.sync.aligned.m8n8.x4.shared.b16 {%0,%1,%2,%3}, [%4];"
                 : "=r"(r[0]), "=r"(r[1]), "=r"(r[2]), "=r"(r[3]) : "r"(addr));
}
__device__ __forceinline__ void mma16816(float* d, const uint32_t* a,
                                         uint32_t b0, uint32_t b1) {
    asm volatile(
        "mma.sync.aligned.m16n8k16.row.col.f32.bf16.bf16.f32 "
        "{%0,%1,%2,%3}, {%4,%5,%6,%7}, {%8,%9}, {%0,%1,%2,%3};"
        : "+f"(d[0]), "+f"(d[1]), "+f"(d[2]), "+f"(d[3])
        : "r"(a[0]), "r"(a[1]), "r"(a[2]), "r"(a[3]), "r"(b0), "r"(b1));
}
__device__ __forceinline__ void cp16(uint32_t dst, const void* src, bool valid) {
    asm volatile("cp.async.cg.shared.global [%0], [%1], 16, %2;"
                 :: "r"(dst), "l"(src), "r"(valid ? 16 : 0) : "memory");
}
#define CP_COMMIT() asm volatile("cp.async.commit_group;" ::: "memory")
#define CP_WAIT2()  asm volatile("cp.async.wait_group 2;" ::: "memory")

// ---------------- pipelined GEMM: C[128x128] += A[128xK] * B[128xK]^T --------
// bf16 hi/lo split: acc += Ah*Bh + Ah*Bl + Al*Bh.  BK=32 per stage, 3 stages.
// Stage layout (32KB): Ah@0, Al@8K, Bh@16K, Bl@24K; rows 64B, SW64 swizzle.
// block = 256 threads = 8 warps as 4(M) x 2(N); warp tile 32x64.
#define STG_SZ 32768
#define GEMM_SMEM (3 * STG_SZ)

__device__ __forceinline__ void gemm_issue(
    char* smem, int stage,
    const __nv_bfloat16* Ah, const __nv_bfloat16* Al, int lda, int aRows,
    const __nv_bfloat16* Bh, const __nv_bfloat16* Bl, int ldb, int bRows,
    int k0, bool kvalid)
{
    const int tid = threadIdx.x;
    const uint32_t sbase = smem_u32(smem) + stage * STG_SZ;
#pragma unroll
    for (int half = 0; half < 2; half++) {
        const int idx = tid + half * 256;        // 0..511
        const int row = idx >> 2, c = idx & 3;   // row 0..127, 16B chunk 0..3
        const uint32_t sw = SWZ64((uint32_t)(row * 64 + c * 16));
        const size_t go = (size_t)row * lda + k0 + c * 8;
        const bool av = kvalid && (row < aRows);
        const bool bv = kvalid && (row < bRows);
        cp16(sbase + sw,          Ah + go, av);
        cp16(sbase + 8192 + sw,   Al + go, av);
        const size_t gb = (size_t)row * ldb + k0 + c * 8;
        cp16(sbase + 16384 + sw,  Bh + gb, bv);
        cp16(sbase + 24576 + sw,  Bl + gb, bv);
    }
}

__device__ __forceinline__ void gemm_compute(
    char* smem, int stage, float acc[2][8][4])
{
    const int tid = threadIdx.x, lane = tid & 31, wid = tid >> 5;
    const int wm = wid >> 1, wn = wid & 1;
    const uint32_t sbase = smem_u32(smem) + stage * STG_SZ;

#pragma unroll
    for (int k16 = 0; k16 < 2; k16++) {
        const int kc = k16 * 2 + (lane >> 4);    // 16B chunk 0..3
        uint32_t ah[2][4], al[2][4];
#pragma unroll
        for (int mt = 0; mt < 2; mt++) {
            const int row = wm * 32 + mt * 16 + (lane & 15);
            const uint32_t off = SWZ64((uint32_t)(row * 64 + kc * 16));
            ldsm4(ah[mt], sbase + off);
            ldsm4(al[mt], sbase + 8192 + off);
        }
#pragma unroll
        for (int nt = 0; nt < 4; nt++) {
            const int row = wn * 64 + nt * 16 + (lane & 15);
            const uint32_t off = SWZ64((uint32_t)(row * 64 + kc * 16));
            uint32_t bh[4], bl[4];
            ldsm4(bh, sbase + 16384 + off);
            ldsm4(bl, sbase + 24576 + off);
#pragma unroll
            for (int mt = 0; mt < 2; mt++)
#pragma unroll
                for (int h = 0; h < 2; h++) {
                    float* d = acc[mt][nt * 2 + h];
                    mma16816(d, ah[mt], bh[h], bh[h + 2]);
                    mma16816(d, ah[mt], bl[h], bl[h + 2]);
                    mma16816(d, al[mt], bh[h], bh[h + 2]);
                }
        }
    }
}

__device__ __forceinline__ void run_gemm(
    const __nv_bfloat16* __restrict__ Ah, const __nv_bfloat16* __restrict__ Al,
    int lda, int aRows,
    const __nv_bfloat16* __restrict__ Bh, const __nv_bfloat16* __restrict__ Bl,
    int ldb, int bRows,
    int kTotal, char* smem, float acc[2][8][4])
{
    const int nk = kTotal >> 5;   // BK=32 stages

#pragma unroll
    for (int s = 0; s < 3; s++) {
        gemm_issue(smem, s, Ah, Al, lda, aRows, Bh, Bl, ldb, bRows,
                   s * 32, s < nk);
        CP_COMMIT();
    }
    for (int k = 0; k < nk; k++) {
        const int st = k % 3;
        CP_WAIT2();
        __syncthreads();
        gemm_compute(smem, st, acc);
        __syncthreads();
        const int kn = k + 3;
        gemm_issue(smem, st, Ah, Al, lda, aRows, Bh, Bl, ldb, bRows,
                   kn * 32, kn < nk);
        CP_COMMIT();
    }
}

// ---------------- 1) depthwise 11x11 SAME conv, 3 filters sharing taps ------
#define SIMG_LD 45
__device__ __forceinline__ void st_split4(__nv_bfloat16* ph, __nv_bfloat16* pl,
                                          const float* v) {
#pragma unroll
    for (int u = 0; u < 4; u += 2) {
        __nv_bfloat162 h, l;
        h.x = __float2bfloat16(v[u]);
        h.y = __float2bfloat16(v[u + 1]);
        l.x = __float2bfloat16(v[u]     - __bfloat162float(h.x));
        l.y = __float2bfloat16(v[u + 1] - __bfloat162float(h.y));
        *(__nv_bfloat162*)(ph + u) = h;
        *(__nv_bfloat162*)(pl + u) = l;
    }
}

__global__ void __launch_bounds__(256) dwconv_kernel(
    const float* __restrict__ x,
    const float* __restrict__ Wq,
    const float* __restrict__ Wk,
    const float* __restrict__ Wv)
{
    const int ch = blockIdx.x;
    const int b  = blockIdx.y;
    const int tid = threadIdx.x;

    __shared__ float simg[(IMGW + 2 * PADR) * SIMG_LD];  // 42 x 45
    __shared__ float wq[KS * KS], wk[KS * KS], wv[KS * KS];

    for (int i = tid; i < (IMGW + 2 * PADR) * SIMG_LD; i += 256) simg[i] = 0.0f;
    if (tid < KS * KS) {
        wq[tid] = Wq[ch * KS * KS + tid];
        wk[tid] = Wk[ch * KS * KS + tid];
        wv[tid] = Wv[ch * KS * KS + tid];
    }
    __syncthreads();

    const float* xim = x + ((size_t)b * NTOK + ch) * HW;
    for (int i = tid; i < HW; i += 256) {
        int r = i >> 5, c = i & 31;
        simg[(r + PADR) * SIMG_LD + (c + PADR)] = xim[i];
    }
    __syncthreads();

    const int r  = tid >> 3;
    const int c0 = (tid & 7) << 2;

    float aq[4] = {0, 0, 0, 0}, ak[4] = {0, 0, 0, 0}, av[4] = {0, 0, 0, 0};

#pragma unroll
    for (int ky = 0; ky < KS; ky++) {
        const float* row = &simg[(r + ky) * SIMG_LD + c0];
        float xr[KS + 3];
#pragma unroll
        for (int t = 0; t < KS + 3; t++) xr[t] = row[t];
#pragma unroll
        for (int kx = 0; kx < KS; kx++) {
            const float wqv = wq[ky * KS + kx];
            const float wkv = wk[ky * KS + kx];
            const float wvv = wv[ky * KS + kx];
#pragma unroll
            for (int u = 0; u < 4; u++) {
                aq[u] = fmaf(xr[kx + u], wqv, aq[u]);
                ak[u] = fmaf(xr[kx + u], wkv, ak[u]);
                av[u] = fmaf(xr[kx + u], wvv, av[u]);
            }
        }
    }

    const size_t base = ((size_t)b * NTOK + ch) * HW + r * IMGW + c0;
    st_split4(&g_qh[base], &g_ql[base], aq);
    st_split4(&g_kh[base], &g_kl[base], ak);
    *(float4*)&g_v[base] = make_float4(av[0], av[1], av[2], av[3]);
}

// ---------------- 2) V transpose: [b,j,s] fp32 -> [b,s,j] bf16 hi/lo --------
__global__ void __launch_bounds__(256) vtrans_kernel()
{
    const int s0 = blockIdx.x * 32;
    const int j0 = blockIdx.y * 32;
    const int b  = blockIdx.z;
    const int tx = threadIdx.x;   // 0..31
    const int ty = threadIdx.y;   // 0..7

    __shared__ float t[32][33];

#pragma unroll
    for (int k = 0; k < 4; k++) {
        int j = j0 + ty + k * 8;
        float v = 0.0f;
        if (j < NTOK) v = g_v[((size_t)b * NTOK + j) * HW + s0 + tx];
        t[ty + k * 8][tx] = v;
    }
    __syncthreads();

#pragma unroll
    for (int k = 0; k < 4; k++) {
        int sr = s0 + ty + k * 8;
        float v = t[tx][ty + k * 8];
        __nv_bfloat16 hi = __float2bfloat16(v);
        float lo = v - __bfloat162float(hi);
        size_t o = ((size_t)b * HW + sr) * ALD + j0 + tx;
        g_vth[o] = hi;
        g_vtl[o] = __float2bfloat16(lo);
    }
}

// ---------------- 3) alpha = Q K^T / 32 via mma.sync ------------------------
__global__ void __launch_bounds__(256) qk_mma_kernel()
{
    extern __shared__ __align__(1024) char smem[];
    const int b  = blockIdx.z;
    const int i0 = blockIdx.y * 128;
    const int j0 = blockIdx.x * 128;
    const int tid = threadIdx.x, lane = tid & 31, wid = tid >> 5;
    const int wm = wid >> 1, wn = wid & 1;

    float acc[2][8][4] = {};
    const size_t ob = (size_t)b * NTOK * HW;
    run_gemm(g_qh + ob + (size_t)i0 * HW, g_ql + ob + (size_t)i0 * HW, HW, NTOK - i0,
             g_kh + ob + (size_t)j0 * HW, g_kl + ob + (size_t)j0 * HW, HW, NTOK - j0,
             HW, smem, acc);

    const float scale = 1.0f / 32.0f;
#pragma unroll
    for (int mt = 0; mt < 2; mt++)
#pragma unroll
        for (int nt = 0; nt < 4; nt++)
#pragma unroll
            for (int h = 0; h < 2; h++) {
                const float* d = acc[mt][nt * 2 + h];
                const int col = j0 + wn * 64 + nt * 16 + h * 8 + (lane & 3) * 2;
                const int r0  = i0 + wm * 32 + mt * 16 + (lane >> 2);
                if (r0 < NTOK) {
                    float* p = &g_alpha[((size_t)b * NTOK + r0) * ALD + col];
                    p[0] = d[0] * scale; p[1] = d[1] * scale;
                }
                if (r0 + 8 < NTOK) {
                    float* p = &g_alpha[((size_t)b * NTOK + r0 + 8) * ALD + col];
                    p[0] = d[2] * scale; p[1] = d[3] * scale;
                }
            }
}

// ---------------- 4) row softmax -> bf16 hi/lo (pads -> 0) ------------------
__global__ void __launch_bounds__(256) softmax_kernel()
{
    const int i = blockIdx.x;
    const int b = blockIdx.y;
    const int tid = threadIdx.x;
    const int lane = tid & 31, wid = tid >> 5;
    const float* a = &g_alpha[((size_t)b * NTOK + i) * ALD];

    __shared__ float sred[8];

    float val = (tid < NTOK) ? a[tid] : -1e30f;

    float m = val;
#pragma unroll
    for (int s = 16; s > 0; s >>= 1) m = fmaxf(m, __shfl_xor_sync(0xFFFFFFFF, m, s));
    if (lane == 0) sred[wid] = m;
    __syncthreads();
    if (wid == 0) {
        float t = sred[lane & 7];
#pragma unroll
        for (int s = 4; s > 0; s >>= 1) t = fmaxf(t, __shfl_xor_sync(0xFFFFFFFF, t, s));
        if (lane == 0) sred[0] = t;
    }
    __syncthreads();
    m = sred[0];
    __syncthreads();

    const float e = (tid < NTOK) ? expf(val - m) : 0.0f;

    float sum = e;
#pragma unroll
    for (int s = 16; s > 0; s >>= 1) sum += __shfl_xor_sync(0xFFFFFFFF, sum, s);
    if (lane == 0) sred[wid] = sum;
    __syncthreads();
    if (wid == 0) {
        float t = sred[lane & 7];
#pragma unroll
        for (int s = 4; s > 0; s >>= 1) t += __shfl_xor_sync(0xFFFFFFFF, t, s);
        if (lane == 0) sred[0] = t;
    }
    __syncthreads();

    const float r = (tid < NTOK) ? e * (1.0f / sred[0]) : 0.0f;
    __nv_bfloat16 hi = __float2bfloat16(r);
    const size_t o = ((size_t)b * NTOK + i) * ALD + tid;
    g_ah[o] = hi;
    g_al[o] = __float2bfloat16(r - __bfloat162float(hi));
}

// ---------------- 5) out = alpha V via mma.sync -----------------------------
__global__ void __launch_bounds__(256) av_mma_kernel(float* __restrict__ out)
{
    extern __shared__ __align__(1024) char smem[];
    const int b  = blockIdx.z;
    const int i0 = blockIdx.y * 128;
    const int s0 = blockIdx.x * 128;
    const int tid = threadIdx.x, lane = tid & 31, wid = tid >> 5;
    const int wm = wid >> 1, wn = wid & 1;

    float acc[2][8][4] = {};
    const size_t ab = (size_t)b * NTOK * ALD;
    const size_t vb = (size_t)b * HW * ALD;
    run_gemm(g_ah + ab + (size_t)i0 * ALD, g_al + ab + (size_t)i0 * ALD, ALD, NTOK - i0,
             g_vth + vb + (size_t)s0 * ALD, g_vtl + vb + (size_t)s0 * ALD, ALD, 128,
             ALD, smem, acc);

#pragma unroll
    for (int mt = 0; mt < 2; mt++)
#pragma unroll
        for (int nt = 0; nt < 4; nt++)
#pragma unroll
            for (int h = 0; h < 2; h++) {
                const float* d = acc[mt][nt * 2 + h];
                const int col = s0 + wn * 64 + nt * 16 + h * 8 + (lane & 3) * 2;
                const int r0  = i0 + wm * 32 + mt * 16 + (lane >> 2);
                if (r0 < NTOK) {
                    float* p = &out[((size_t)b * NTOK + r0) * HW + col];
                    p[0] = d[0]; p[1] = d[1];
                }
                if (r0 + 8 < NTOK) {
                    float* p = &out[((size_t)b * NTOK + r0 + 8) * HW + col];
                    p[0] = d[2]; p[1] = d[3];
                }
            }
}

// ---------------- launch ----------------------------------------------------
extern "C" void kernel_launch(void* const* d_in, const int* in_sizes, int n_in,
                              void* d_out, int out_size)
{
    const float* x  = (const float*)d_in[0];
    const float* Wq = (const float*)d_in[1];
    const float* Wk = (const float*)d_in[2];
    const float* Wv = (const float*)d_in[3];
    float* out = (float*)d_out;

    cudaFuncSetAttribute(qk_mma_kernel,
                         cudaFuncAttributeMaxDynamicSharedMemorySize, GEMM_SMEM);
    cudaFuncSetAttribute(av_mma_kernel,
                         cudaFuncAttributeMaxDynamicSharedMemorySize, GEMM_SMEM);

    dim3 gConv(NTOK, BATCH);
    dwconv_kernel<<<gConv, 256>>>(x, Wq, Wk, Wv);

    dim3 gT(32, 8, BATCH);
    vtrans_kernel<<<gT, dim3(32, 8)>>>();

    dim3 gQK(2, 2, BATCH);
    qk_mma_kernel<<<gQK, 256, GEMM_SMEM>>>();

    dim3 gS(NTOK, BATCH);
    softmax_kernel<<<gS, 256>>>();

    dim3 gAV(8, 2, BATCH);
    av_mma_kernel<<<gAV, 256, GEMM_SMEM>>>(out);
}

// round 9
// speedup vs baseline: 1.8797x; 1.1258x over previous
#include <cuda_runtime.h>
#include <cuda_fp16.h>
#include <cstdint>
#include <cstddef>

#define BATCH 64
#define NTOK  197
#define HW    1024
#define IMGW  32
#define KS    11
#define PADR  5
#define ALD   256   // padded token dim (j) for alpha / V^T

// ---------------- scratch (static device globals; no allocs allowed) --------
__device__ __half g_qh[(size_t)BATCH * NTOK * HW];
__device__ __half g_ql[(size_t)BATCH * NTOK * HW];
__device__ __half g_kh[(size_t)BATCH * NTOK * HW];
__device__ __half g_kl[(size_t)BATCH * NTOK * HW];
__device__ float  g_v [(size_t)BATCH * NTOK * HW];
__device__ __half g_vth[(size_t)BATCH * HW * ALD];   // V^T hi  [b][s][j]
__device__ __half g_vtl[(size_t)BATCH * HW * ALD];   // V^T lo
__device__ float  g_alpha[(size_t)BATCH * NTOK * ALD];
__device__ __half g_ah[(size_t)BATCH * NTOK * ALD];  // softmax(alpha) hi only

// ---------------- helpers ----------------------------------------------------
__device__ __forceinline__ uint32_t smem_u32(const void* p) {
    uint32_t a;
    asm("{ .reg .u64 t; cvta.to.shared.u64 t, %1; cvt.u32.u64 %0, t; }"
        : "=r"(a) : "l"(p));
    return a;
}
// swizzle for 64-byte rows (8-row/512B atom)
#define SWZ64(o) ((o) ^ (((o) >> 3) & 0x30))

__device__ __forceinline__ void ldsm4(uint32_t* r, uint32_t addr) {
    asm volatile("ldmatrix.sync.aligned.m8n8.x4.shared.b16 {%0,%1,%2,%3}, [%4];"
                 : "=r"(r[0]), "=r"(r[1]), "=r"(r[2]), "=r"(r[3]) : "r"(addr));
}
__device__ __forceinline__ void mma16816(float* d, const uint32_t* a,
                                         uint32_t b0, uint32_t b1) {
    asm volatile(
        "mma.sync.aligned.m16n8k16.row.col.f32.f16.f16.f32 "
        "{%0,%1,%2,%3}, {%4,%5,%6,%7}, {%8,%9}, {%0,%1,%2,%3};"
        : "+f"(d[0]), "+f"(d[1]), "+f"(d[2]), "+f"(d[3])
        : "r"(a[0]), "r"(a[1]), "r"(a[2]), "r"(a[3]), "r"(b0), "r"(b1));
}
__device__ __forceinline__ void cp16(uint32_t dst, const void* src, bool valid) {
    asm volatile("cp.async.cg.shared.global [%0], [%1], 16, %2;"
                 :: "r"(dst), "l"(src), "r"(valid ? 16 : 0) : "memory");
}
#define CP_COMMIT() asm volatile("cp.async.commit_group;" ::: "memory")
#define CP_WAIT2()  asm volatile("cp.async.wait_group 2;" ::: "memory")

// ================== QK pipelined GEMM (3-term fp16 split) ====================
// Stage (32KB): Ah@0, Al@8K, Bh@16K, Bl@24K; rows 64B, SW64.  3 stages.
#define STG_QK 32768
#define SMEM_QK (3 * STG_QK)

__device__ __forceinline__ void qk_issue(
    char* smem, int stage,
    const __half* Ah, const __half* Al, int lda, int aRows,
    const __half* Bh, const __half* Bl, int ldb, int bRows,
    int k0, bool kvalid)
{
    const int tid = threadIdx.x;
    const uint32_t sbase = smem_u32(smem) + stage * STG_QK;
#pragma unroll
    for (int half_ = 0; half_ < 2; half_++) {
        const int idx = tid + half_ * 256;
        const int row = idx >> 2, c = idx & 3;
        const uint32_t sw = SWZ64((uint32_t)(row * 64 + c * 16));
        const size_t go = (size_t)row * lda + k0 + c * 8;
        const bool av = kvalid && (row < aRows);
        const bool bv = kvalid && (row < bRows);
        cp16(sbase + sw,         Ah + go, av);
        cp16(sbase + 8192 + sw,  Al + go, av);
        const size_t gb = (size_t)row * ldb + k0 + c * 8;
        cp16(sbase + 16384 + sw, Bh + gb, bv);
        cp16(sbase + 24576 + sw, Bl + gb, bv);
    }
}

__device__ __forceinline__ void qk_compute(char* smem, int stage,
                                           float acc[2][8][4])
{
    const int tid = threadIdx.x, lane = tid & 31, wid = tid >> 5;
    const int wm = wid >> 1, wn = wid & 1;
    const uint32_t sbase = smem_u32(smem) + stage * STG_QK;

#pragma unroll
    for (int k16 = 0; k16 < 2; k16++) {
        const int kc = k16 * 2 + (lane >> 4);
        uint32_t ah[2][4], al[2][4];
#pragma unroll
        for (int mt = 0; mt < 2; mt++) {
            const int row = wm * 32 + mt * 16 + (lane & 15);
            const uint32_t off = SWZ64((uint32_t)(row * 64 + kc * 16));
            ldsm4(ah[mt], sbase + off);
            ldsm4(al[mt], sbase + 8192 + off);
        }
#pragma unroll
        for (int nt = 0; nt < 4; nt++) {
            const int row = wn * 64 + nt * 16 + (lane & 15);
            const uint32_t off = SWZ64((uint32_t)(row * 64 + kc * 16));
            uint32_t bh[4], bl[4];
            ldsm4(bh, sbase + 16384 + off);
            ldsm4(bl, sbase + 24576 + off);
#pragma unroll
            for (int mt = 0; mt < 2; mt++)
#pragma unroll
                for (int h = 0; h < 2; h++) {
                    float* d = acc[mt][nt * 2 + h];
                    mma16816(d, ah[mt], bh[h], bh[h + 2]);
                    mma16816(d, ah[mt], bl[h], bl[h + 2]);
                    mma16816(d, al[mt], bh[h], bh[h + 2]);
                }
        }
    }
}

__device__ __forceinline__ void run_qk(
    const __half* __restrict__ Ah, const __half* __restrict__ Al,
    int lda, int aRows,
    const __half* __restrict__ Bh, const __half* __restrict__ Bl,
    int ldb, int bRows,
    int kTotal, char* smem, float acc[2][8][4])
{
    const int nk = kTotal >> 5;
#pragma unroll
    for (int s = 0; s < 3; s++) {
        qk_issue(smem, s, Ah, Al, lda, aRows, Bh, Bl, ldb, bRows, s * 32, s < nk);
        CP_COMMIT();
    }
    for (int k = 0; k < nk; k++) {
        const int st = k % 3;
        CP_WAIT2();
        __syncthreads();
        qk_compute(smem, st, acc);
        __syncthreads();
        const int kn = k + 3;
        qk_issue(smem, st, Ah, Al, lda, aRows, Bh, Bl, ldb, bRows, kn * 32, kn < nk);
        CP_COMMIT();
    }
}

// ================== AV pipelined GEMM (2-term: Ah*Bh + Ah*Bl) ================
// Stage (24KB): Ah@0, Bh@8K, Bl@16K.  3 stages.
#define STG_AV 24576
#define SMEM_AV (3 * STG_AV)

__device__ __forceinline__ void av_issue(
    char* smem, int stage,
    const __half* Ah, int lda, int aRows,
    const __half* Bh, const __half* Bl, int ldb, int bRows,
    int k0, bool kvalid)
{
    const int tid = threadIdx.x;
    const uint32_t sbase = smem_u32(smem) + stage * STG_AV;
#pragma unroll
    for (int half_ = 0; half_ < 2; half_++) {
        const int idx = tid + half_ * 256;
        const int row = idx >> 2, c = idx & 3;
        const uint32_t sw = SWZ64((uint32_t)(row * 64 + c * 16));
        const size_t go = (size_t)row * lda + k0 + c * 8;
        const bool av = kvalid && (row < aRows);
        const bool bv = kvalid && (row < bRows);
        cp16(sbase + sw,         Ah + go, av);
        const size_t gb = (size_t)row * ldb + k0 + c * 8;
        cp16(sbase + 8192 + sw,  Bh + gb, bv);
        cp16(sbase + 16384 + sw, Bl + gb, bv);
    }
}

__device__ __forceinline__ void av_compute(char* smem, int stage,
                                           float acc[2][8][4])
{
    const int tid = threadIdx.x, lane = tid & 31, wid = tid >> 5;
    const int wm = wid >> 1, wn = wid & 1;
    const uint32_t sbase = smem_u32(smem) + stage * STG_AV;

#pragma unroll
    for (int k16 = 0; k16 < 2; k16++) {
        const int kc = k16 * 2 + (lane >> 4);
        uint32_t ah[2][4];
#pragma unroll
        for (int mt = 0; mt < 2; mt++) {
            const int row = wm * 32 + mt * 16 + (lane & 15);
            const uint32_t off = SWZ64((uint32_t)(row * 64 + kc * 16));
            ldsm4(ah[mt], sbase + off);
        }
#pragma unroll
        for (int nt = 0; nt < 4; nt++) {
            const int row = wn * 64 + nt * 16 + (lane & 15);
            const uint32_t off = SWZ64((uint32_t)(row * 64 + kc * 16));
            uint32_t bh[4], bl[4];
            ldsm4(bh, sbase + 8192 + off);
            ldsm4(bl, sbase + 16384 + off);
#pragma unroll
            for (int mt = 0; mt < 2; mt++)
#pragma unroll
                for (int h = 0; h < 2; h++) {
                    float* d = acc[mt][nt * 2 + h];
                    mma16816(d, ah[mt], bh[h], bh[h + 2]);
                    mma16816(d, ah[mt], bl[h], bl[h + 2]);
                }
        }
    }
}

__device__ __forceinline__ void run_av(
    const __half* __restrict__ Ah, int lda, int aRows,
    const __half* __restrict__ Bh, const __half* __restrict__ Bl,
    int ldb, int bRows,
    int kTotal, char* smem, float acc[2][8][4])
{
    const int nk = kTotal >> 5;
#pragma unroll
    for (int s = 0; s < 3; s++) {
        av_issue(smem, s, Ah, lda, aRows, Bh, Bl, ldb, bRows, s * 32, s < nk);
        CP_COMMIT();
    }
    for (int k = 0; k < nk; k++) {
        const int st = k % 3;
        CP_WAIT2();
        __syncthreads();
        av_compute(smem, st, acc);
        __syncthreads();
        const int kn = k + 3;
        av_issue(smem, st, Ah, lda, aRows, Bh, Bl, ldb, bRows, kn * 32, kn < nk);
        CP_COMMIT();
    }
}

// ---------------- 1) depthwise 11x11 SAME conv, 3 filters sharing taps ------
#define SIMG_LD 48   // float4-aligned rows; LDS.128 phases conflict-free
#define WPK_LD  36   // 12 kx slots * 3 filters, 16B-aligned rows

__device__ __forceinline__ void st_split4h(__half* ph, __half* pl,
                                           const float* v) {
#pragma unroll
    for (int u = 0; u < 4; u += 2) {
        __half2 h, l;
        h.x = __float2half_rn(v[u]);
        h.y = __float2half_rn(v[u + 1]);
        l.x = __float2half_rn(v[u]     - __half2float(h.x));
        l.y = __float2half_rn(v[u + 1] - __half2float(h.y));
        *(__half2*)(ph + u) = h;
        *(__half2*)(pl + u) = l;
    }
}

__global__ void __launch_bounds__(256) dwconv_kernel(
    const float* __restrict__ x,
    const float* __restrict__ Wq,
    const float* __restrict__ Wk,
    const float* __restrict__ Wv)
{
    const int ch = blockIdx.x;
    const int b  = blockIdx.y;
    const int tid = threadIdx.x;

    __shared__ __align__(16) float simg[(IMGW + 2 * PADR) * SIMG_LD];  // 42x48
    __shared__ __align__(16) float wpk[KS * WPK_LD];

    for (int i = tid; i < (IMGW + 2 * PADR) * SIMG_LD; i += 256) simg[i] = 0.0f;
    if (tid < KS * KS) {
        const int ky = tid / KS, kx = tid % KS;
        const int o = ky * WPK_LD + kx * 3;
        wpk[o + 0] = Wq[ch * KS * KS + tid];
        wpk[o + 1] = Wk[ch * KS * KS + tid];
        wpk[o + 2] = Wv[ch * KS * KS + tid];
    }
    __syncthreads();

    const float* xim = x + ((size_t)b * NTOK + ch) * HW;
    for (int i = tid; i < HW; i += 256) {
        int r = i >> 5, c = i & 31;
        simg[(r + PADR) * SIMG_LD + (c + PADR)] = xim[i];
    }
    __syncthreads();

    const int r  = tid >> 3;          // 0..31
    const int c0 = (tid & 7) << 2;    // 0,4,...,28

    float aq[4] = {0, 0, 0, 0}, ak[4] = {0, 0, 0, 0}, av[4] = {0, 0, 0, 0};

#pragma unroll
    for (int ky = 0; ky < KS; ky++) {
        const float* row = &simg[(r + ky) * SIMG_LD + c0];   // 16B-aligned
        float xr[16];
#pragma unroll
        for (int g = 0; g < 4; g++) {
            const float4 v4 = *(const float4*)(row + g * 4);
            xr[g * 4 + 0] = v4.x; xr[g * 4 + 1] = v4.y;
            xr[g * 4 + 2] = v4.z; xr[g * 4 + 3] = v4.w;
        }
        float wrow[36];
        const float* wsrc = &wpk[ky * WPK_LD];
#pragma unroll
        for (int g = 0; g < 9; g++) {
            const float4 w4 = *(const float4*)(wsrc + g * 4);
            wrow[g * 4 + 0] = w4.x; wrow[g * 4 + 1] = w4.y;
            wrow[g * 4 + 2] = w4.z; wrow[g * 4 + 3] = w4.w;
        }
#pragma unroll
        for (int kx = 0; kx < KS; kx++) {
            const float wqv = wrow[kx * 3 + 0];
            const float wkv = wrow[kx * 3 + 1];
            const float wvv = wrow[kx * 3 + 2];
#pragma unroll
            for (int u = 0; u < 4; u++) {
                aq[u] = fmaf(xr[kx + u], wqv, aq[u]);
                ak[u] = fmaf(xr[kx + u], wkv, ak[u]);
                av[u] = fmaf(xr[kx + u], wvv, av[u]);
            }
        }
    }

    const size_t base = ((size_t)b * NTOK + ch) * HW + r * IMGW + c0;
    st_split4h(&g_qh[base], &g_ql[base], aq);
    st_split4h(&g_kh[base], &g_kl[base], ak);
    *(float4*)&g_v[base] = make_float4(av[0], av[1], av[2], av[3]);
}

// ---------------- 2) V transpose: [b,j,s] fp32 -> [b,s,j] fp16 hi/lo --------
__global__ void __launch_bounds__(256) vtrans_kernel()
{
    const int s0 = blockIdx.x * 32;
    const int j0 = blockIdx.y * 32;
    const int b  = blockIdx.z;
    const int tx = threadIdx.x;   // 0..31
    const int ty = threadIdx.y;   // 0..7

    __shared__ float t[32][33];

#pragma unroll
    for (int k = 0; k < 4; k++) {
        int j = j0 + ty + k * 8;
        float v = 0.0f;
        if (j < NTOK) v = g_v[((size_t)b * NTOK + j) * HW + s0 + tx];
        t[ty + k * 8][tx] = v;
    }
    __syncthreads();

#pragma unroll
    for (int k = 0; k < 4; k++) {
        int sr = s0 + ty + k * 8;
        float v = t[tx][ty + k * 8];
        __half hi = __float2half_rn(v);
        float lo = v - __half2float(hi);
        size_t o = ((size_t)b * HW + sr) * ALD + j0 + tx;
        g_vth[o] = hi;
        g_vtl[o] = __float2half_rn(lo);
    }
}

// ---------------- 3) alpha = Q K^T / 32 via mma.sync (fp16 3-term) ----------
__global__ void __launch_bounds__(256) qk_mma_kernel()
{
    extern __shared__ __align__(1024) char smem[];
    const int b  = blockIdx.z;
    const int i0 = blockIdx.y * 128;
    const int j0 = blockIdx.x * 128;
    const int tid = threadIdx.x, lane = tid & 31, wid = tid >> 5;
    const int wm = wid >> 1, wn = wid & 1;

    float acc[2][8][4] = {};
    const size_t ob = (size_t)b * NTOK * HW;
    run_qk(g_qh + ob + (size_t)i0 * HW, g_ql + ob + (size_t)i0 * HW, HW, NTOK - i0,
           g_kh + ob + (size_t)j0 * HW, g_kl + ob + (size_t)j0 * HW, HW, NTOK - j0,
           HW, smem, acc);

    const float scale = 1.0f / 32.0f;
#pragma unroll
    for (int mt = 0; mt < 2; mt++)
#pragma unroll
        for (int nt = 0; nt < 4; nt++)
#pragma unroll
            for (int h = 0; h < 2; h++) {
                const float* d = acc[mt][nt * 2 + h];
                const int col = j0 + wn * 64 + nt * 16 + h * 8 + (lane & 3) * 2;
                const int r0  = i0 + wm * 32 + mt * 16 + (lane >> 2);
                if (r0 < NTOK) {
                    float* p = &g_alpha[((size_t)b * NTOK + r0) * ALD + col];
                    p[0] = d[0] * scale; p[1] = d[1] * scale;
                }
                if (r0 + 8 < NTOK) {
                    float* p = &g_alpha[((size_t)b * NTOK + r0 + 8) * ALD + col];
                    p[0] = d[2] * scale; p[1] = d[3] * scale;
                }
            }
}

// ---------------- 4) row softmax -> fp16 hi (pads -> 0) ---------------------
__global__ void __launch_bounds__(256) softmax_kernel()
{
    const int i = blockIdx.x;
    const int b = blockIdx.y;
    const int tid = threadIdx.x;
    const int lane = tid & 31, wid = tid >> 5;
    const float* a = &g_alpha[((size_t)b * NTOK + i) * ALD];

    __shared__ float sred[8];

    float val = (tid < NTOK) ? a[tid] : -1e30f;

    float m = val;
#pragma unroll
    for (int s = 16; s > 0; s >>= 1) m = fmaxf(m, __shfl_xor_sync(0xFFFFFFFF, m, s));
    if (lane == 0) sred[wid] = m;
    __syncthreads();
    if (wid == 0) {
        float t = sred[lane & 7];
#pragma unroll
        for (int s = 4; s > 0; s >>= 1) t = fmaxf(t, __shfl_xor_sync(0xFFFFFFFF, t, s));
        if (lane == 0) sred[0] = t;
    }
    __syncthreads();
    m = sred[0];
    __syncthreads();

    const float e = (tid < NTOK) ? expf(val - m) : 0.0f;

    float sum = e;
#pragma unroll
    for (int s = 16; s > 0; s >>= 1) sum += __shfl_xor_sync(0xFFFFFFFF, sum, s);
    if (lane == 0) sred[wid] = sum;
    __syncthreads();
    if (wid == 0) {
        float t = sred[lane & 7];
#pragma unroll
        for (int s = 4; s > 0; s >>= 1) t += __shfl_xor_sync(0xFFFFFFFF, t, s);
        if (lane == 0) sred[0] = t;
    }
    __syncthreads();

    const float r = (tid < NTOK) ? e * (1.0f / sred[0]) : 0.0f;
    g_ah[((size_t)b * NTOK + i) * ALD + tid] = __float2half_rn(r);
}

// ---------------- 5) out = alpha V via mma.sync (fp16 2-term) ---------------
__global__ void __launch_bounds__(256) av_mma_kernel(float* __restrict__ out)
{
    extern __shared__ __align__(1024) char smem[];
    const int b  = blockIdx.z;
    const int i0 = blockIdx.y * 128;
    const int s0 = blockIdx.x * 128;
    const int tid = threadIdx.x, lane = tid & 31, wid = tid >> 5;
    const int wm = wid >> 1, wn = wid & 1;

    float acc[2][8][4] = {};
    const size_t ab = (size_t)b * NTOK * ALD;
    const size_t vb = (size_t)b * HW * ALD;
    run_av(g_ah + ab + (size_t)i0 * ALD, ALD, NTOK - i0,
           g_vth + vb + (size_t)s0 * ALD, g_vtl + vb + (size_t)s0 * ALD, ALD, 128,
           ALD, smem, acc);

#pragma unroll
    for (int mt = 0; mt < 2; mt++)
#pragma unroll
        for (int nt = 0; nt < 4; nt++)
#pragma unroll
            for (int h = 0; h < 2; h++) {
                const float* d = acc[mt][nt * 2 + h];
                const int col = s0 + wn * 64 + nt * 16 + h * 8 + (lane & 3) * 2;
                const int r0  = i0 + wm * 32 + mt * 16 + (lane >> 2);
                if (r0 < NTOK) {
                    float* p = &out[((size_t)b * NTOK + r0) * HW + col];
                    p[0] = d[0]; p[1] = d[1];
                }
                if (r0 + 8 < NTOK) {
                    float* p = &out[((size_t)b * NTOK + r0 + 8) * HW + col];
                    p[0] = d[2]; p[1] = d[3];
                }
            }
}

// ---------------- launch ----------------------------------------------------
extern "C" void kernel_launch(void* const* d_in, const int* in_sizes, int n_in,
                              void* d_out, int out_size)
{
    const float* x  = (const float*)d_in[0];
    const float* Wq = (const float*)d_in[1];
    const float* Wk = (const float*)d_in[2];
    const float* Wv = (const float*)d_in[3];
    float* out = (float*)d_out;

    cudaFuncSetAttribute(qk_mma_kernel,
                         cudaFuncAttributeMaxDynamicSharedMemorySize, SMEM_QK);
    cudaFuncSetAttribute(av_mma_kernel,
                         cudaFuncAttributeMaxDynamicSharedMemorySize, SMEM_AV);

    dim3 gConv(NTOK, BATCH);
    dwconv_kernel<<<gConv, 256>>>(x, Wq, Wk, Wv);

    dim3 gT(32, 8, BATCH);
    vtrans_kernel<<<gT, dim3(32, 8)>>>();

    dim3 gQK(2, 2, BATCH);
    qk_mma_kernel<<<gQK, 256, SMEM_QK>>>();

    dim3 gS(NTOK, BATCH);
    softmax_kernel<<<gS, 256>>>();

    dim3 gAV(8, 2, BATCH);
    av_mma_kernel<<<gAV, 256, SMEM_AV>>>(out);
}

// round 10
// speedup vs baseline: 2.2489x; 1.1965x over previous
#include <cuda_runtime.h>
#include <cuda_fp16.h>
#include <cstdint>
#include <cstddef>

#define BATCH 64
#define NTOK  197
#define HW    1024
#define IMGW  32
#define KS    11
#define PADR  5
#define ALD   256   // padded token dim (j) for alpha
#define AVK   224   // ceil(197/32)*32 — AV K extent

// ---------------- scratch (static device globals; no allocs allowed) --------
__device__ __half g_qh[(size_t)BATCH * NTOK * HW];
__device__ __half g_kh[(size_t)BATCH * NTOK * HW];
__device__ __half g_kl[(size_t)BATCH * NTOK * HW];
__device__ __half g_vh[(size_t)BATCH * NTOK * HW];   // V hi [b][j][s]
__device__ __half g_vl[(size_t)BATCH * NTOK * HW];   // V lo
__device__ float  g_alpha[(size_t)BATCH * NTOK * ALD];
__device__ __half g_ah[(size_t)BATCH * NTOK * ALD];  // softmax(alpha)

// ---------------- helpers ----------------------------------------------------
__device__ __forceinline__ uint32_t smem_u32(const void* p) {
    uint32_t a;
    asm("{ .reg .u64 t; cvta.to.shared.u64 t, %1; cvt.u32.u64 %0, t; }"
        : "=r"(a) : "l"(p));
    return a;
}
// swizzle for 64-byte rows (8-row/512B atom)
#define SWZ64(o) ((o) ^ (((o) >> 3) & 0x30))
// swizzle for 256-byte rows: XOR 16B-granule with (row&7)
#define SWZ256(o) ((o) ^ ((((o) >> 8) & 7) << 4))

__device__ __forceinline__ void ldsm4(uint32_t* r, uint32_t addr) {
    asm volatile("ldmatrix.sync.aligned.m8n8.x4.shared.b16 {%0,%1,%2,%3}, [%4];"
                 : "=r"(r[0]), "=r"(r[1]), "=r"(r[2]), "=r"(r[3]) : "r"(addr));
}
__device__ __forceinline__ void ldsm4t(uint32_t* r, uint32_t addr) {
    asm volatile("ldmatrix.sync.aligned.m8n8.x4.trans.shared.b16 {%0,%1,%2,%3}, [%4];"
                 : "=r"(r[0]), "=r"(r[1]), "=r"(r[2]), "=r"(r[3]) : "r"(addr));
}
__device__ __forceinline__ void mma16816(float* d, const uint32_t* a,
                                         uint32_t b0, uint32_t b1) {
    asm volatile(
        "mma.sync.aligned.m16n8k16.row.col.f32.f16.f16.f32 "
        "{%0,%1,%2,%3}, {%4,%5,%6,%7}, {%8,%9}, {%0,%1,%2,%3};"
        : "+f"(d[0]), "+f"(d[1]), "+f"(d[2]), "+f"(d[3])
        : "r"(a[0]), "r"(a[1]), "r"(a[2]), "r"(a[3]), "r"(b0), "r"(b1));
}
__device__ __forceinline__ void cp16(uint32_t dst, const void* src, bool valid) {
    asm volatile("cp.async.cg.shared.global [%0], [%1], 16, %2;"
                 :: "r"(dst), "l"(src), "r"(valid ? 16 : 0) : "memory");
}
#define CP_COMMIT() asm volatile("cp.async.commit_group;" ::: "memory")
#define CP_WAIT2()  asm volatile("cp.async.wait_group 2;" ::: "memory")

// Stage (24KB): A@0 (8K), Bh@8K, Bl@16K.  3 stages = 72KB for both GEMMs.
#define STG_SZ 24576
#define GEMM_SMEM (3 * STG_SZ)

// ================== QK pipelined GEMM (2-term: Ah*Bh + Ah*Bl) ================
// A = Q[i][k] row-major, B = K[j][k] row-major (both 64B smem rows, SW64).
__device__ __forceinline__ void qk_issue(
    char* smem, int stage,
    const __half* Ah, int lda, int aRows,
    const __half* Bh, const __half* Bl, int ldb, int bRows,
    int k0, bool kvalid)
{
    const int tid = threadIdx.x;
    const uint32_t sbase = smem_u32(smem) + stage * STG_SZ;
#pragma unroll
    for (int g = 0; g < 2; g++) {
        const int idx = tid + g * 256;
        const int row = idx >> 2, c = idx & 3;
        const uint32_t sw = SWZ64((uint32_t)(row * 64 + c * 16));
        const size_t go = (size_t)row * lda + k0 + c * 8;
        cp16(sbase + sw,         Ah + go, kvalid && (row < aRows));
        const size_t gb = (size_t)row * ldb + k0 + c * 8;
        const bool bv = kvalid && (row < bRows);
        cp16(sbase + 8192 + sw,  Bh + gb, bv);
        cp16(sbase + 16384 + sw, Bl + gb, bv);
    }
}

__device__ __forceinline__ void qk_compute(char* smem, int stage,
                                           float acc[2][8][4])
{
    const int tid = threadIdx.x, lane = tid & 31, wid = tid >> 5;
    const int wm = wid >> 1, wn = wid & 1;
    const uint32_t sbase = smem_u32(smem) + stage * STG_SZ;

#pragma unroll
    for (int k16 = 0; k16 < 2; k16++) {
        const int kc = k16 * 2 + (lane >> 4);
        uint32_t ah[2][4];
#pragma unroll
        for (int mt = 0; mt < 2; mt++) {
            const int row = wm * 32 + mt * 16 + (lane & 15);
            ldsm4(ah[mt], sbase + SWZ64((uint32_t)(row * 64 + kc * 16)));
        }
#pragma unroll
        for (int nt = 0; nt < 4; nt++) {
            const int row = wn * 64 + nt * 16 + (lane & 15);
            const uint32_t off = SWZ64((uint32_t)(row * 64 + kc * 16));
            uint32_t bh[4], bl[4];
            ldsm4(bh, sbase + 8192 + off);
            ldsm4(bl, sbase + 16384 + off);
#pragma unroll
            for (int mt = 0; mt < 2; mt++)
#pragma unroll
                for (int h = 0; h < 2; h++) {
                    float* d = acc[mt][nt * 2 + h];
                    mma16816(d, ah[mt], bh[h], bh[h + 2]);
                    mma16816(d, ah[mt], bl[h], bl[h + 2]);
                }
        }
    }
}

__device__ __forceinline__ void run_qk(
    const __half* __restrict__ Ah, int lda, int aRows,
    const __half* __restrict__ Bh, const __half* __restrict__ Bl,
    int ldb, int bRows,
    int kTotal, char* smem, float acc[2][8][4])
{
    const int nk = kTotal >> 5;
#pragma unroll
    for (int s = 0; s < 3; s++) {
        qk_issue(smem, s, Ah, lda, aRows, Bh, Bl, ldb, bRows, s * 32, s < nk);
        CP_COMMIT();
    }
    for (int k = 0; k < nk; k++) {
        const int st = k % 3;
        CP_WAIT2();
        __syncthreads();
        qk_compute(smem, st, acc);
        __syncthreads();
        const int kn = k + 3;
        qk_issue(smem, st, Ah, lda, aRows, Bh, Bl, ldb, bRows, kn * 32, kn < nk);
        CP_COMMIT();
    }
}

// ================== AV pipelined GEMM (A=alpha, B=V [K=j][N=s] via trans) ====
// B stage tile: 32 j-rows x 128 s-cols fp16 = 8KB (256B rows, SWZ256).
__device__ __forceinline__ void av_issue(
    char* smem, int stage,
    const __half* Ah, int lda, int aRows,
    const __half* Vh, const __half* Vl, int ldv, int s0,
    int k0, bool kvalid)
{
    const int tid = threadIdx.x;
    const uint32_t sbase = smem_u32(smem) + stage * STG_SZ;
    // A: 128 rows x 4 chunks of 16B (64B rows, SW64)
#pragma unroll
    for (int g = 0; g < 2; g++) {
        const int idx = tid + g * 256;
        const int row = idx >> 2, c = idx & 3;
        const uint32_t sw = SWZ64((uint32_t)(row * 64 + c * 16));
        cp16(sbase + sw, Ah + (size_t)row * lda + k0 + c * 8,
             kvalid && (row < aRows));
    }
    // B: 32 j-rows x 16 chunks of 16B (256B rows, SWZ256)
#pragma unroll
    for (int g = 0; g < 2; g++) {
        const int idx = tid + g * 256;
        const int row = idx >> 4, c = idx & 15;
        const uint32_t sw = SWZ256((uint32_t)(row * 256 + c * 16));
        const int j = k0 + row;
        const bool v = (j < NTOK);
        const size_t go = (size_t)j * ldv + s0 + c * 8;
        cp16(sbase + 8192 + sw,  Vh + go, v);
        cp16(sbase + 16384 + sw, Vl + go, v);
    }
}

__device__ __forceinline__ void av_compute(char* smem, int stage,
                                           float acc[2][8][4])
{
    const int tid = threadIdx.x, lane = tid & 31, wid = tid >> 5;
    const int wm = wid >> 1, wn = wid & 1;
    const uint32_t sbase = smem_u32(smem) + stage * STG_SZ;

#pragma unroll
    for (int k16 = 0; k16 < 2; k16++) {
        const int kc = k16 * 2 + (lane >> 4);
        uint32_t ah[2][4];
#pragma unroll
        for (int mt = 0; mt < 2; mt++) {
            const int row = wm * 32 + mt * 16 + (lane & 15);
            ldsm4(ah[mt], sbase + SWZ64((uint32_t)(row * 64 + kc * 16)));
        }
        // trans B: krow = k16*16 + (lane&15); n byte = warp/nt base + (lane>>4)*16
        const int krow = k16 * 16 + (lane & 15);
#pragma unroll
        for (int nt = 0; nt < 4; nt++) {
            const uint32_t nb = (uint32_t)(wn * 128 + nt * 32 + (lane >> 4) * 16);
            const uint32_t off = SWZ256((uint32_t)(krow * 256) + nb);
            uint32_t bh[4], bl[4];
            ldsm4t(bh, sbase + 8192 + off);
            ldsm4t(bl, sbase + 16384 + off);
#pragma unroll
            for (int mt = 0; mt < 2; mt++)
#pragma unroll
                for (int h = 0; h < 2; h++) {
                    float* d = acc[mt][nt * 2 + h];
                    mma16816(d, ah[mt], bh[h * 2], bh[h * 2 + 1]);
                    mma16816(d, ah[mt], bl[h * 2], bl[h * 2 + 1]);
                }
        }
    }
}

__device__ __forceinline__ void run_av(
    const __half* __restrict__ Ah, int lda, int aRows,
    const __half* __restrict__ Vh, const __half* __restrict__ Vl,
    int ldv, int s0,
    int kTotal, char* smem, float acc[2][8][4])
{
    const int nk = kTotal >> 5;
#pragma unroll
    for (int s = 0; s < 3; s++) {
        av_issue(smem, s, Ah, lda, aRows, Vh, Vl, ldv, s0, s * 32, s < nk);
        CP_COMMIT();
    }
    for (int k = 0; k < nk; k++) {
        const int st = k % 3;
        CP_WAIT2();
        __syncthreads();
        av_compute(smem, st, acc);
        __syncthreads();
        const int kn = k + 3;
        av_issue(smem, st, Ah, lda, aRows, Vh, Vl, ldv, s0, kn * 32, kn < nk);
        CP_COMMIT();
    }
}

// ---------------- 1) depthwise 11x11 SAME conv, 3 filters sharing taps ------
#define SIMG_LD 48
#define WPK_LD  36

__device__ __forceinline__ void st_hi4(__half* ph, const float* v) {
#pragma unroll
    for (int u = 0; u < 4; u += 2) {
        __half2 h;
        h.x = __float2half_rn(v[u]);
        h.y = __float2half_rn(v[u + 1]);
        *(__half2*)(ph + u) = h;
    }
}
__device__ __forceinline__ void st_split4h(__half* ph, __half* pl,
                                           const float* v) {
#pragma unroll
    for (int u = 0; u < 4; u += 2) {
        __half2 h, l;
        h.x = __float2half_rn(v[u]);
        h.y = __float2half_rn(v[u + 1]);
        l.x = __float2half_rn(v[u]     - __half2float(h.x));
        l.y = __float2half_rn(v[u + 1] - __half2float(h.y));
        *(__half2*)(ph + u) = h;
        *(__half2*)(pl + u) = l;
    }
}

__global__ void __launch_bounds__(256) dwconv_kernel(
    const float* __restrict__ x,
    const float* __restrict__ Wq,
    const float* __restrict__ Wk,
    const float* __restrict__ Wv)
{
    const int ch = blockIdx.x;
    const int b  = blockIdx.y;
    const int tid = threadIdx.x;

    __shared__ __align__(16) float simg[(IMGW + 2 * PADR) * SIMG_LD];  // 42x48
    __shared__ __align__(16) float wpk[KS * WPK_LD];

    for (int i = tid; i < (IMGW + 2 * PADR) * SIMG_LD; i += 256) simg[i] = 0.0f;
    if (tid < KS * KS) {
        const int ky = tid / KS, kx = tid % KS;
        const int o = ky * WPK_LD + kx * 3;
        wpk[o + 0] = Wq[ch * KS * KS + tid];
        wpk[o + 1] = Wk[ch * KS * KS + tid];
        wpk[o + 2] = Wv[ch * KS * KS + tid];
    }
    __syncthreads();

    const float* xim = x + ((size_t)b * NTOK + ch) * HW;
    for (int i = tid; i < HW; i += 256) {
        int r = i >> 5, c = i & 31;
        simg[(r + PADR) * SIMG_LD + (c + PADR)] = xim[i];
    }
    __syncthreads();

    const int r  = tid >> 3;
    const int c0 = (tid & 7) << 2;

    float aq[4] = {0, 0, 0, 0}, ak[4] = {0, 0, 0, 0}, av[4] = {0, 0, 0, 0};

#pragma unroll
    for (int ky = 0; ky < KS; ky++) {
        const float* row = &simg[(r + ky) * SIMG_LD + c0];
        float xr[16];
#pragma unroll
        for (int g = 0; g < 4; g++) {
            const float4 v4 = *(const float4*)(row + g * 4);
            xr[g * 4 + 0] = v4.x; xr[g * 4 + 1] = v4.y;
            xr[g * 4 + 2] = v4.z; xr[g * 4 + 3] = v4.w;
        }
        float wrow[36];
        const float* wsrc = &wpk[ky * WPK_LD];
#pragma unroll
        for (int g = 0; g < 9; g++) {
            const float4 w4 = *(const float4*)(wsrc + g * 4);
            wrow[g * 4 + 0] = w4.x; wrow[g * 4 + 1] = w4.y;
            wrow[g * 4 + 2] = w4.z; wrow[g * 4 + 3] = w4.w;
        }
#pragma unroll
        for (int kx = 0; kx < KS; kx++) {
            const float wqv = wrow[kx * 3 + 0];
            const float wkv = wrow[kx * 3 + 1];
            const float wvv = wrow[kx * 3 + 2];
#pragma unroll
            for (int u = 0; u < 4; u++) {
                aq[u] = fmaf(xr[kx + u], wqv, aq[u]);
                ak[u] = fmaf(xr[kx + u], wkv, ak[u]);
                av[u] = fmaf(xr[kx + u], wvv, av[u]);
            }
        }
    }

    const size_t base = ((size_t)b * NTOK + ch) * HW + r * IMGW + c0;
    st_hi4(&g_qh[base], aq);
    st_split4h(&g_kh[base], &g_kl[base], ak);
    st_split4h(&g_vh[base], &g_vl[base], av);
}

// ---------------- 2) alpha = Q K^T / 32 via mma.sync (fp16 2-term) ----------
__global__ void __launch_bounds__(256) qk_mma_kernel()
{
    extern __shared__ __align__(1024) char smem[];
    const int b  = blockIdx.z;
    const int i0 = blockIdx.y * 128;
    const int j0 = blockIdx.x * 128;
    const int tid = threadIdx.x, lane = tid & 31, wid = tid >> 5;
    const int wm = wid >> 1, wn = wid & 1;

    float acc[2][8][4] = {};
    const size_t ob = (size_t)b * NTOK * HW;
    run_qk(g_qh + ob + (size_t)i0 * HW, HW, NTOK - i0,
           g_kh + ob + (size_t)j0 * HW, g_kl + ob + (size_t)j0 * HW, HW, NTOK - j0,
           HW, smem, acc);

    const float scale = 1.0f / 32.0f;
#pragma unroll
    for (int mt = 0; mt < 2; mt++)
#pragma unroll
        for (int nt = 0; nt < 4; nt++)
#pragma unroll
            for (int h = 0; h < 2; h++) {
                const float* d = acc[mt][nt * 2 + h];
                const int col = j0 + wn * 64 + nt * 16 + h * 8 + (lane & 3) * 2;
                const int r0  = i0 + wm * 32 + mt * 16 + (lane >> 2);
                if (r0 < NTOK) {
                    float* p = &g_alpha[((size_t)b * NTOK + r0) * ALD + col];
                    p[0] = d[0] * scale; p[1] = d[1] * scale;
                }
                if (r0 + 8 < NTOK) {
                    float* p = &g_alpha[((size_t)b * NTOK + r0 + 8) * ALD + col];
                    p[0] = d[2] * scale; p[1] = d[3] * scale;
                }
            }
}

// ---------------- 3) row softmax -> fp16 (pads -> 0) ------------------------
__global__ void __launch_bounds__(256) softmax_kernel()
{
    const int i = blockIdx.x;
    const int b = blockIdx.y;
    const int tid = threadIdx.x;
    const int lane = tid & 31, wid = tid >> 5;
    const float* a = &g_alpha[((size_t)b * NTOK + i) * ALD];

    __shared__ float sred[8];

    float val = (tid < NTOK) ? a[tid] : -1e30f;

    float m = val;
#pragma unroll
    for (int s = 16; s > 0; s >>= 1) m = fmaxf(m, __shfl_xor_sync(0xFFFFFFFF, m, s));
    if (lane == 0) sred[wid] = m;
    __syncthreads();
    if (wid == 0) {
        float t = sred[lane & 7];
#pragma unroll
        for (int s = 4; s > 0; s >>= 1) t = fmaxf(t, __shfl_xor_sync(0xFFFFFFFF, t, s));
        if (lane == 0) sred[0] = t;
    }
    __syncthreads();
    m = sred[0];
    __syncthreads();

    const float e = (tid < NTOK) ? expf(val - m) : 0.0f;

    float sum = e;
#pragma unroll
    for (int s = 16; s > 0; s >>= 1) sum += __shfl_xor_sync(0xFFFFFFFF, sum, s);
    if (lane == 0) sred[wid] = sum;
    __syncthreads();
    if (wid == 0) {
        float t = sred[lane & 7];
#pragma unroll
        for (int s = 4; s > 0; s >>= 1) t += __shfl_xor_sync(0xFFFFFFFF, t, s);
        if (lane == 0) sred[0] = t;
    }
    __syncthreads();

    const float r = (tid < NTOK) ? e * (1.0f / sred[0]) : 0.0f;
    g_ah[((size_t)b * NTOK + i) * ALD + tid] = __float2half_rn(r);
}

// ---------------- 4) out = alpha V via mma.sync (trans-B) -------------------
__global__ void __launch_bounds__(256) av_mma_kernel(float* __restrict__ out)
{
    extern __shared__ __align__(1024) char smem[];
    const int b  = blockIdx.z;
    const int i0 = blockIdx.y * 128;
    const int s0 = blockIdx.x * 128;
    const int tid = threadIdx.x, lane = tid & 31, wid = tid >> 5;
    const int wm = wid >> 1, wn = wid & 1;

    float acc[2][8][4] = {};
    const size_t ab = (size_t)b * NTOK * ALD;
    const size_t vb = (size_t)b * NTOK * HW;
    run_av(g_ah + ab + (size_t)i0 * ALD, ALD, NTOK - i0,
           g_vh + vb, g_vl + vb, HW, s0,
           AVK, smem, acc);

#pragma unroll
    for (int mt = 0; mt < 2; mt++)
#pragma unroll
        for (int nt = 0; nt < 4; nt++)
#pragma unroll
            for (int h = 0; h < 2; h++) {
                const float* d = acc[mt][nt * 2 + h];
                const int col = s0 + wn * 64 + nt * 16 + h * 8 + (lane & 3) * 2;
                const int r0  = i0 + wm * 32 + mt * 16 + (lane >> 2);
                if (r0 < NTOK) {
                    float* p = &out[((size_t)b * NTOK + r0) * HW + col];
                    p[0] = d[0]; p[1] = d[1];
                }
                if (r0 + 8 < NTOK) {
                    float* p = &out[((size_t)b * NTOK + r0 + 8) * HW + col];
                    p[0] = d[2]; p[1] = d[3];
                }
            }
}

// ---------------- launch ----------------------------------------------------
extern "C" void kernel_launch(void* const* d_in, const int* in_sizes, int n_in,
                              void* d_out, int out_size)
{
    const float* x  = (const float*)d_in[0];
    const float* Wq = (const float*)d_in[1];
    const float* Wk = (const float*)d_in[2];
    const float* Wv = (const float*)d_in[3];
    float* out = (float*)d_out;

    cudaFuncSetAttribute(qk_mma_kernel,
                         cudaFuncAttributeMaxDynamicSharedMemorySize, GEMM_SMEM);
    cudaFuncSetAttribute(av_mma_kernel,
                         cudaFuncAttributeMaxDynamicSharedMemorySize, GEMM_SMEM);

    dim3 gConv(NTOK, BATCH);
    dwconv_kernel<<<gConv, 256>>>(x, Wq, Wk, Wv);

    dim3 gQK(2, 2, BATCH);
    qk_mma_kernel<<<gQK, 256, GEMM_SMEM>>>();

    dim3 gS(NTOK, BATCH);
    softmax_kernel<<<gS, 256>>>();

    dim3 gAV(8, 2, BATCH);
    av_mma_kernel<<<gAV, 256, GEMM_SMEM>>>(out);
}

// round 11
// speedup vs baseline: 2.5404x; 1.1296x over previous
#include <cuda_runtime.h>
#include <cuda_fp16.h>
#include <cstdint>
#include <cstddef>

#define BATCH 64
#define NTOK  197
#define HW    1024
#define IMGW  32
#define KS    11
#define PADR  5
#define ALD   256   // padded token dim (j) for alpha
#define AVK   224   // ceil(197/32)*32 — AV K extent

// ---------------- scratch (static device globals; no allocs allowed) --------
__device__ __half g_qh[(size_t)BATCH * NTOK * HW];
__device__ __half g_kh[(size_t)BATCH * NTOK * HW];
__device__ __half g_vh[(size_t)BATCH * NTOK * HW];   // V hi [b][j][s]
__device__ __half g_vl[(size_t)BATCH * NTOK * HW];   // V lo
__device__ __half g_ah[(size_t)BATCH * NTOK * ALD];  // softmax(alpha)

// ---------------- helpers ----------------------------------------------------
__device__ __forceinline__ uint32_t smem_u32(const void* p) {
    uint32_t a;
    asm("{ .reg .u64 t; cvta.to.shared.u64 t, %1; cvt.u32.u64 %0, t; }"
        : "=r"(a) : "l"(p));
    return a;
}
#define SWZ64(o) ((o) ^ (((o) >> 3) & 0x30))
#define SWZ256(o) ((o) ^ ((((o) >> 8) & 7) << 4))

__device__ __forceinline__ void ldsm4(uint32_t* r, uint32_t addr) {
    asm volatile("ldmatrix.sync.aligned.m8n8.x4.shared.b16 {%0,%1,%2,%3}, [%4];"
                 : "=r"(r[0]), "=r"(r[1]), "=r"(r[2]), "=r"(r[3]) : "r"(addr));
}
__device__ __forceinline__ void ldsm4t(uint32_t* r, uint32_t addr) {
    asm volatile("ldmatrix.sync.aligned.m8n8.x4.trans.shared.b16 {%0,%1,%2,%3}, [%4];"
                 : "=r"(r[0]), "=r"(r[1]), "=r"(r[2]), "=r"(r[3]) : "r"(addr));
}
__device__ __forceinline__ void mma16816(float* d, const uint32_t* a,
                                         uint32_t b0, uint32_t b1) {
    asm volatile(
        "mma.sync.aligned.m16n8k16.row.col.f32.f16.f16.f32 "
        "{%0,%1,%2,%3}, {%4,%5,%6,%7}, {%8,%9}, {%0,%1,%2,%3};"
        : "+f"(d[0]), "+f"(d[1]), "+f"(d[2]), "+f"(d[3])
        : "r"(a[0]), "r"(a[1]), "r"(a[2]), "r"(a[3]), "r"(b0), "r"(b1));
}
__device__ __forceinline__ void cp16(uint32_t dst, const void* src, bool valid) {
    asm volatile("cp.async.cg.shared.global [%0], [%1], 16, %2;"
                 :: "r"(dst), "l"(src), "r"(valid ? 16 : 0) : "memory");
}
#define CP_COMMIT() asm volatile("cp.async.commit_group;" ::: "memory")
#define CP_WAIT2()  asm volatile("cp.async.wait_group 2;" ::: "memory")

// ================== fused QK + softmax =======================================
// C[64 x 256] = Q[64 x 1024] * K[256 x 1024]^T, then row softmax -> g_ah fp16.
// Stage (20KB): A(Q) 4KB @0, B(K) 16KB @4K; 64B rows, SW64; 3 stages.
// 8 warps as 2(M) x 4(N); warp tile 32x64.
#define FQ_STG  20480
#define FQ_SMEM (3 * FQ_STG + 1024)   // + red[64][4] floats

__device__ __forceinline__ void fqk_issue(
    char* smem, int stage, const __half* Q, int qRows, const __half* K,
    int k0, bool kvalid)
{
    const int tid = threadIdx.x;
    const uint32_t sbase = smem_u32(smem) + stage * FQ_STG;
    {
        const int row = tid >> 2, c = tid & 3;
        cp16(sbase + SWZ64((uint32_t)(row * 64 + c * 16)),
             Q + (size_t)row * HW + k0 + c * 8, kvalid && (row < qRows));
    }
#pragma unroll
    for (int g = 0; g < 4; g++) {
        const int idx = tid + g * 256;
        const int row = idx >> 2, c = idx & 3;
        cp16(sbase + 4096 + SWZ64((uint32_t)(row * 64 + c * 16)),
             K + (size_t)row * HW + k0 + c * 8, kvalid && (row < NTOK));
    }
}

__device__ __forceinline__ void fqk_compute(char* smem, int stage,
                                            float acc[2][8][4])
{
    const int tid = threadIdx.x, lane = tid & 31, wid = tid >> 5;
    const int wm = wid >> 2, wn = wid & 3;
    const uint32_t sbase = smem_u32(smem) + stage * FQ_STG;

#pragma unroll
    for (int k16 = 0; k16 < 2; k16++) {
        const int kc = k16 * 2 + (lane >> 4);
        uint32_t ah[2][4];
#pragma unroll
        for (int mt = 0; mt < 2; mt++) {
            const int row = wm * 32 + mt * 16 + (lane & 15);
            ldsm4(ah[mt], sbase + SWZ64((uint32_t)(row * 64 + kc * 16)));
        }
#pragma unroll
        for (int nt = 0; nt < 4; nt++) {
            const int row = wn * 64 + nt * 16 + (lane & 15);
            uint32_t bh[4];
            ldsm4(bh, sbase + 4096 + SWZ64((uint32_t)(row * 64 + kc * 16)));
#pragma unroll
            for (int mt = 0; mt < 2; mt++)
#pragma unroll
                for (int h = 0; h < 2; h++)
                    mma16816(acc[mt][nt * 2 + h], ah[mt], bh[h], bh[h + 2]);
        }
    }
}

__global__ void __launch_bounds__(256) qk_softmax_kernel()
{
    extern __shared__ __align__(1024) char smem[];
    const int b  = blockIdx.y;
    const int i0 = blockIdx.x * 64;
    const int tid = threadIdx.x, lane = tid & 31, wid = tid >> 5;
    const int wm = wid >> 2, wn = wid & 3;
    float* red = (float*)(smem + 3 * FQ_STG);   // [64][4]

    const size_t ob = (size_t)b * NTOK * HW;
    const __half* Q = g_qh + ob + (size_t)i0 * HW;
    const __half* K = g_kh + ob;

    float acc[2][8][4] = {};
    const int nk = HW >> 5;   // 32 stages

#pragma unroll
    for (int s = 0; s < 3; s++) {
        fqk_issue(smem, s, Q, NTOK - i0, K, s * 32, s < nk);
        CP_COMMIT();
    }
    for (int k = 0; k < nk; k++) {
        const int st = k % 3;
        CP_WAIT2();
        __syncthreads();
        fqk_compute(smem, st, acc);
        __syncthreads();
        const int kn = k + 3;
        fqk_issue(smem, st, Q, NTOK - i0, K, kn * 32, kn < nk);
        CP_COMMIT();
    }

    // ---- row softmax over j (cols) ----
    // value (mt, nb, d): row = i0-rel wm*32+mt*16+(d>>1)*8+(lane>>2)
    //                    col = wn*64+(nb>>1)*16+(nb&1)*8+(lane&3)*2+(d&1)
    const float scale = 1.0f / 32.0f;

    // mask invalid cols
#pragma unroll
    for (int mt = 0; mt < 2; mt++)
#pragma unroll
        for (int nb = 0; nb < 8; nb++)
#pragma unroll
            for (int d = 0; d < 4; d++) {
                const int col = wn * 64 + (nb >> 1) * 16 + (nb & 1) * 8 +
                                (lane & 3) * 2 + (d & 1);
                if (col >= NTOK) acc[mt][nb][d] = -1e30f;
            }

    // row max: quad shuffle + cross-warp (4 n-warps) via smem
    float mrow[2][2];
#pragma unroll
    for (int mt = 0; mt < 2; mt++)
#pragma unroll
        for (int rr = 0; rr < 2; rr++) {
            float mx = -1e30f;
#pragma unroll
            for (int nb = 0; nb < 8; nb++) {
                mx = fmaxf(mx, acc[mt][nb][rr * 2 + 0]);
                mx = fmaxf(mx, acc[mt][nb][rr * 2 + 1]);
            }
            mx = fmaxf(mx, __shfl_xor_sync(0xFFFFFFFF, mx, 1));
            mx = fmaxf(mx, __shfl_xor_sync(0xFFFFFFFF, mx, 2));
            if ((lane & 3) == 0) {
                const int rowl = wm * 32 + mt * 16 + rr * 8 + (lane >> 2);
                red[rowl * 4 + wn] = mx;
            }
        }
    __syncthreads();
#pragma unroll
    for (int mt = 0; mt < 2; mt++)
#pragma unroll
        for (int rr = 0; rr < 2; rr++) {
            const int rowl = wm * 32 + mt * 16 + rr * 8 + (lane >> 2);
            mrow[mt][rr] = fmaxf(fmaxf(red[rowl * 4 + 0], red[rowl * 4 + 1]),
                                 fmaxf(red[rowl * 4 + 2], red[rowl * 4 + 3]));
        }
    __syncthreads();

    // exp + row sum
    float inv[2][2];
#pragma unroll
    for (int mt = 0; mt < 2; mt++)
#pragma unroll
        for (int rr = 0; rr < 2; rr++) {
            float sm = 0.0f;
#pragma unroll
            for (int nb = 0; nb < 8; nb++)
#pragma unroll
                for (int c = 0; c < 2; c++) {
                    float e = expf((acc[mt][nb][rr * 2 + c] - mrow[mt][rr]) * scale);
                    acc[mt][nb][rr * 2 + c] = e;
                    sm += e;
                }
            sm += __shfl_xor_sync(0xFFFFFFFF, sm, 1);
            sm += __shfl_xor_sync(0xFFFFFFFF, sm, 2);
            if ((lane & 3) == 0) {
                const int rowl = wm * 32 + mt * 16 + rr * 8 + (lane >> 2);
                red[rowl * 4 + wn] = sm;
            }
        }
    __syncthreads();
#pragma unroll
    for (int mt = 0; mt < 2; mt++)
#pragma unroll
        for (int rr = 0; rr < 2; rr++) {
            const int rowl = wm * 32 + mt * 16 + rr * 8 + (lane >> 2);
            const float tot = red[rowl * 4 + 0] + red[rowl * 4 + 1] +
                              red[rowl * 4 + 2] + red[rowl * 4 + 3];
            inv[mt][rr] = 1.0f / tot;
        }

    // normalized fp16 stores
#pragma unroll
    for (int mt = 0; mt < 2; mt++)
#pragma unroll
        for (int rr = 0; rr < 2; rr++) {
            const int rowg = i0 + wm * 32 + mt * 16 + rr * 8 + (lane >> 2);
            if (rowg >= NTOK) continue;
            __half* arow = &g_ah[((size_t)b * NTOK + rowg) * ALD];
#pragma unroll
            for (int nb = 0; nb < 8; nb++) {
                const int col = wn * 64 + (nb >> 1) * 16 + (nb & 1) * 8 +
                                (lane & 3) * 2;
                __half2 h;
                h.x = __float2half_rn(acc[mt][nb][rr * 2 + 0] * inv[mt][rr]);
                h.y = __float2half_rn(acc[mt][nb][rr * 2 + 1] * inv[mt][rr]);
                *(__half2*)&arow[col] = h;
            }
        }
}

// ================== AV pipelined GEMM (A=alpha, B=V [K=j][N=s] via trans) ====
#define STG_SZ 24576
#define GEMM_SMEM (3 * STG_SZ)

__device__ __forceinline__ void av_issue(
    char* smem, int stage,
    const __half* Ah, int lda, int aRows,
    const __half* Vh, const __half* Vl, int ldv, int s0,
    int k0, bool kvalid)
{
    const int tid = threadIdx.x;
    const uint32_t sbase = smem_u32(smem) + stage * STG_SZ;
#pragma unroll
    for (int g = 0; g < 2; g++) {
        const int idx = tid + g * 256;
        const int row = idx >> 2, c = idx & 3;
        const uint32_t sw = SWZ64((uint32_t)(row * 64 + c * 16));
        cp16(sbase + sw, Ah + (size_t)row * lda + k0 + c * 8,
             kvalid && (row < aRows));
    }
#pragma unroll
    for (int g = 0; g < 2; g++) {
        const int idx = tid + g * 256;
        const int row = idx >> 4, c = idx & 15;
        const uint32_t sw = SWZ256((uint32_t)(row * 256 + c * 16));
        const int j = k0 + row;
        const bool v = (j < NTOK);
        const size_t go = (size_t)j * ldv + s0 + c * 8;
        cp16(sbase + 8192 + sw,  Vh + go, v);
        cp16(sbase + 16384 + sw, Vl + go, v);
    }
}

__device__ __forceinline__ void av_compute(char* smem, int stage,
                                           float acc[2][8][4])
{
    const int tid = threadIdx.x, lane = tid & 31, wid = tid >> 5;
    const int wm = wid >> 1, wn = wid & 1;
    const uint32_t sbase = smem_u32(smem) + stage * STG_SZ;

#pragma unroll
    for (int k16 = 0; k16 < 2; k16++) {
        const int kc = k16 * 2 + (lane >> 4);
        uint32_t ah[2][4];
#pragma unroll
        for (int mt = 0; mt < 2; mt++) {
            const int row = wm * 32 + mt * 16 + (lane & 15);
            ldsm4(ah[mt], sbase + SWZ64((uint32_t)(row * 64 + kc * 16)));
        }
        const int krow = k16 * 16 + (lane & 15);
#pragma unroll
        for (int nt = 0; nt < 4; nt++) {
            const uint32_t nb = (uint32_t)(wn * 128 + nt * 32 + (lane >> 4) * 16);
            const uint32_t off = SWZ256((uint32_t)(krow * 256) + nb);
            uint32_t bh[4], bl[4];
            ldsm4t(bh, sbase + 8192 + off);
            ldsm4t(bl, sbase + 16384 + off);
#pragma unroll
            for (int mt = 0; mt < 2; mt++)
#pragma unroll
                for (int h = 0; h < 2; h++) {
                    float* d = acc[mt][nt * 2 + h];
                    mma16816(d, ah[mt], bh[h * 2], bh[h * 2 + 1]);
                    mma16816(d, ah[mt], bl[h * 2], bl[h * 2 + 1]);
                }
        }
    }
}

__device__ __forceinline__ void run_av(
    const __half* __restrict__ Ah, int lda, int aRows,
    const __half* __restrict__ Vh, const __half* __restrict__ Vl,
    int ldv, int s0, int kTotal, char* smem, float acc[2][8][4])
{
    const int nk = kTotal >> 5;
#pragma unroll
    for (int s = 0; s < 3; s++) {
        av_issue(smem, s, Ah, lda, aRows, Vh, Vl, ldv, s0, s * 32, s < nk);
        CP_COMMIT();
    }
    for (int k = 0; k < nk; k++) {
        const int st = k % 3;
        CP_WAIT2();
        __syncthreads();
        av_compute(smem, st, acc);
        __syncthreads();
        const int kn = k + 3;
        av_issue(smem, st, Ah, lda, aRows, Vh, Vl, ldv, s0, kn * 32, kn < nk);
        CP_COMMIT();
    }
}

// ---------------- 1) depthwise 11x11 SAME conv --------------------------------
#define SIMG_LD 48
#define WPK_LD  36

__device__ __forceinline__ void st_hi4(__half* ph, const float* v) {
#pragma unroll
    for (int u = 0; u < 4; u += 2) {
        __half2 h;
        h.x = __float2half_rn(v[u]);
        h.y = __float2half_rn(v[u + 1]);
        *(__half2*)(ph + u) = h;
    }
}
__device__ __forceinline__ void st_split4h(__half* ph, __half* pl,
                                           const float* v) {
#pragma unroll
    for (int u = 0; u < 4; u += 2) {
        __half2 h, l;
        h.x = __float2half_rn(v[u]);
        h.y = __float2half_rn(v[u + 1]);
        l.x = __float2half_rn(v[u]     - __half2float(h.x));
        l.y = __float2half_rn(v[u + 1] - __half2float(h.y));
        *(__half2*)(ph + u) = h;
        *(__half2*)(pl + u) = l;
    }
}

__global__ void __launch_bounds__(256) dwconv_kernel(
    const float* __restrict__ x,
    const float* __restrict__ Wq,
    const float* __restrict__ Wk,
    const float* __restrict__ Wv)
{
    const int ch = blockIdx.x;
    const int b  = blockIdx.y;
    const int tid = threadIdx.x;

    __shared__ __align__(16) float simg[(IMGW + 2 * PADR) * SIMG_LD];
    __shared__ __align__(16) float wpk[KS * WPK_LD];

    for (int i = tid; i < (IMGW + 2 * PADR) * SIMG_LD; i += 256) simg[i] = 0.0f;
    if (tid < KS * KS) {
        const int ky = tid / KS, kx = tid % KS;
        const int o = ky * WPK_LD + kx * 3;
        wpk[o + 0] = Wq[ch * KS * KS + tid];
        wpk[o + 1] = Wk[ch * KS * KS + tid];
        wpk[o + 2] = Wv[ch * KS * KS + tid];
    }
    __syncthreads();

    const float* xim = x + ((size_t)b * NTOK + ch) * HW;
    for (int i = tid; i < HW; i += 256) {
        int r = i >> 5, c = i & 31;
        simg[(r + PADR) * SIMG_LD + (c + PADR)] = xim[i];
    }
    __syncthreads();

    const int r  = tid >> 3;
    const int c0 = (tid & 7) << 2;

    float aq[4] = {0, 0, 0, 0}, ak[4] = {0, 0, 0, 0}, av[4] = {0, 0, 0, 0};

#pragma unroll
    for (int ky = 0; ky < KS; ky++) {
        const float* row = &simg[(r + ky) * SIMG_LD + c0];
        float xr[16];
#pragma unroll
        for (int g = 0; g < 4; g++) {
            const float4 v4 = *(const float4*)(row + g * 4);
            xr[g * 4 + 0] = v4.x; xr[g * 4 + 1] = v4.y;
            xr[g * 4 + 2] = v4.z; xr[g * 4 + 3] = v4.w;
        }
        float wrow[36];
        const float* wsrc = &wpk[ky * WPK_LD];
#pragma unroll
        for (int g = 0; g < 9; g++) {
            const float4 w4 = *(const float4*)(wsrc + g * 4);
            wrow[g * 4 + 0] = w4.x; wrow[g * 4 + 1] = w4.y;
            wrow[g * 4 + 2] = w4.z; wrow[g * 4 + 3] = w4.w;
        }
#pragma unroll
        for (int kx = 0; kx < KS; kx++) {
            const float wqv = wrow[kx * 3 + 0];
            const float wkv = wrow[kx * 3 + 1];
            const float wvv = wrow[kx * 3 + 2];
#pragma unroll
            for (int u = 0; u < 4; u++) {
                aq[u] = fmaf(xr[kx + u], wqv, aq[u]);
                ak[u] = fmaf(xr[kx + u], wkv, ak[u]);
                av[u] = fmaf(xr[kx + u], wvv, av[u]);
            }
        }
    }

    const size_t base = ((size_t)b * NTOK + ch) * HW + r * IMGW + c0;
    st_hi4(&g_qh[base], aq);
    st_hi4(&g_kh[base], ak);
    st_split4h(&g_vh[base], &g_vl[base], av);
}

// ---------------- out = alpha V via mma.sync (trans-B) ----------------------
__global__ void __launch_bounds__(256) av_mma_kernel(float* __restrict__ out)
{
    extern __shared__ __align__(1024) char smem[];
    const int b  = blockIdx.z;
    const int i0 = blockIdx.y * 128;
    const int s0 = blockIdx.x * 128;
    const int tid = threadIdx.x, lane = tid & 31, wid = tid >> 5;
    const int wm = wid >> 1, wn = wid & 1;

    float acc[2][8][4] = {};
    const size_t ab = (size_t)b * NTOK * ALD;
    const size_t vb = (size_t)b * NTOK * HW;
    run_av(g_ah + ab + (size_t)i0 * ALD, ALD, NTOK - i0,
           g_vh + vb, g_vl + vb, HW, s0, AVK, smem, acc);

#pragma unroll
    for (int mt = 0; mt < 2; mt++)
#pragma unroll
        for (int nt = 0; nt < 4; nt++)
#pragma unroll
            for (int h = 0; h < 2; h++) {
                const float* d = acc[mt][nt * 2 + h];
                const int col = s0 + wn * 64 + nt * 16 + h * 8 + (lane & 3) * 2;
                const int r0  = i0 + wm * 32 + mt * 16 + (lane >> 2);
                if (r0 < NTOK) {
                    float* p = &out[((size_t)b * NTOK + r0) * HW + col];
                    p[0] = d[0]; p[1] = d[1];
                }
                if (r0 + 8 < NTOK) {
                    float* p = &out[((size_t)b * NTOK + r0 + 8) * HW + col];
                    p[0] = d[2]; p[1] = d[3];
                }
            }
}

// ---------------- launch ----------------------------------------------------
extern "C" void kernel_launch(void* const* d_in, const int* in_sizes, int n_in,
                              void* d_out, int out_size)
{
    const float* x  = (const float*)d_in[0];
    const float* Wq = (const float*)d_in[1];
    const float* Wk = (const float*)d_in[2];
    const float* Wv = (const float*)d_in[3];
    float* out = (float*)d_out;

    cudaFuncSetAttribute(qk_softmax_kernel,
                         cudaFuncAttributeMaxDynamicSharedMemorySize, FQ_SMEM);
    cudaFuncSetAttribute(av_mma_kernel,
                         cudaFuncAttributeMaxDynamicSharedMemorySize, GEMM_SMEM);

    dim3 gConv(NTOK, BATCH);
    dwconv_kernel<<<gConv, 256>>>(x, Wq, Wk, Wv);

    dim3 gQK(4, BATCH);
    qk_softmax_kernel<<<gQK, 256, FQ_SMEM>>>();

    dim3 gAV(8, 2, BATCH);
    av_mma_kernel<<<gAV, 256, GEMM_SMEM>>>(out);
}